// round 6
// baseline (speedup 1.0000x reference)
#include <cuda_runtime.h>
#include <math.h>

#define D 64
#define MAXN 100000
#define MAXE 1100000

// ---------------- static device scratch ----------------
__device__ float g_x  [MAXN * D];    // x_in = concat(u, v)
__device__ float g_su [MAXN * 128];  // per-node: [0..63]=x@Ui, [64..127]=x@Vj+bv
__device__ float g_xvi[MAXN * D];
__device__ float g_y  [MAXN * D];    // stage1 output
__device__ float g_y2 [MAXN * D];    // stage2 output
__device__ float g_stats1[2 * D];
__device__ float g_stats2[2 * D];
// CSR (edges sorted by destination)
__device__ int g_cnt[MAXN + 1];
__device__ int g_off[MAXN + 1];
__device__ int g_cur[MAXN];
__device__ int g_srcSorted[MAXE];
__device__ int g_bsum[512];

#define FMA4(ACC, A, B) do { (ACC).x += (A)*(B).x; (ACC).y += (A)*(B).y; \
                             (ACC).z += (A)*(B).z; (ACC).w += (A)*(B).w; } while(0)

// ================= CSR build =================
__global__ void hist_kernel(const int* __restrict__ ee, int nE)
{
    int e = blockIdx.x * blockDim.x + threadIdx.x;
    if (e < nE) atomicAdd(&g_cnt[ee[e]], 1);
}

__global__ void scan_block_kernel(int n)
{
    __shared__ int sh[256];
    int tid = threadIdx.x;
    int i = blockIdx.x * 256 + tid;
    int v = (i < n) ? g_cnt[i] : 0;
    sh[tid] = v;
    __syncthreads();
    #pragma unroll
    for (int ofs = 1; ofs < 256; ofs <<= 1) {
        int x = (tid >= ofs) ? sh[tid - ofs] : 0;
        __syncthreads();
        sh[tid] += x;
        __syncthreads();
    }
    if (i < n) g_off[i] = sh[tid] - v;
    if (tid == 255) g_bsum[blockIdx.x] = sh[255];
}

__global__ void scan_add_kernel(int n)
{
    __shared__ int s_prefix;
    const int bid = blockIdx.x;
    if (threadIdx.x < 32) {
        int s = 0;
        for (int i = threadIdx.x; i < bid; i += 32) s += g_bsum[i];
        #pragma unroll
        for (int o = 16; o; o >>= 1) s += __shfl_down_sync(0xffffffffu, s, o);
        if (threadIdx.x == 0) s_prefix = s;
    }
    __syncthreads();
    int i = bid * 256 + threadIdx.x;
    if (i < n) {
        int o = g_off[i] + s_prefix;
        g_off[i] = o;
        g_cur[i] = o;
        if (i == n - 1) g_off[n] = o + g_cnt[i];
    }
}

__global__ void scatter_kernel(const int* __restrict__ es, const int* __restrict__ ee, int nE)
{
    int e = blockIdx.x * blockDim.x + threadIdx.x;
    if (e < nE) {
        int d = ee[e];
        int p = atomicAdd(&g_cur[d], 1);
        g_srcSorted[p] = es[e];
    }
}

// ================= fused 4-matrix GEMM: X[64-row tile] @ [Ui|Uj|Vi|Vj] =================
// 256 threads = 32 tx * 8 ty; thread tile: 8 rows x (float4 cols tx and tx+32).
// tx<16: owns 4 cols of Ui + 4 cols of Vi; tx>=16: Uj + Vj. All LDS conflict-free.
#define XS_STRIDE 68
#define GEMM4_SMEM (64*256*4 + 64*XS_STRIDE*4)

template<bool BN>
__global__ void __launch_bounds__(256, 2)
gemm4_kernel(const float* __restrict__ X,
             const float* __restrict__ Ui, const float* __restrict__ Uj,
             const float* __restrict__ Vi, const float* __restrict__ Vj,
             const float* __restrict__ bu, const float* __restrict__ bv,
             const float* __restrict__ stats, const float* __restrict__ gamma,
             const float* __restrict__ beta,
             float* __restrict__ su, float* __restrict__ y,
             float* __restrict__ xvi,
             int n)
{
    extern __shared__ float smem[];
    float* Ws = smem;              // [64][256]
    float* Xs = smem + 64 * 256;   // [64][XS_STRIDE]
    __shared__ float s_scale[64], s_shift[64];
    const int tid = threadIdx.x;
    const int rowBase = blockIdx.x * 64;

    if (BN) {
        if (tid < 64) {
            float fn = 1.f / (float)n;
            float mean = stats[tid] * fn;
            float var  = stats[64 + tid] * fn - mean * mean;
            float sc = gamma[tid] * rsqrtf(var + 1e-3f);
            s_scale[tid] = sc;
            s_shift[tid] = beta[tid] - mean * sc;
        }
        __syncthreads();
    }

    {
        const float* mats[4] = {Ui, Uj, Vi, Vj};
        #pragma unroll
        for (int m = 0; m < 4; m++) {
            const float4* src = (const float4*)mats[m];
            for (int i = tid; i < 1024; i += 256) {
                int k = i >> 4, j4 = i & 15;
                ((float4*)(Ws + k * 256 + m * 64))[j4] = src[k * 16 + j4];
            }
        }
        for (int i = tid; i < 1024; i += 256) {
            int r = i >> 4, c4 = i & 15;
            int row = rowBase + r;
            float4 v = make_float4(0.f, 0.f, 0.f, 0.f);
            if (row < n) v = ((const float4*)X)[row * 16 + c4];
            if (BN) {
                int c = c4 * 4;
                v.x = fmaxf(v.x * s_scale[c+0] + s_shift[c+0], 0.f);
                v.y = fmaxf(v.y * s_scale[c+1] + s_shift[c+1], 0.f);
                v.z = fmaxf(v.z * s_scale[c+2] + s_shift[c+2], 0.f);
                v.w = fmaxf(v.w * s_scale[c+3] + s_shift[c+3], 0.f);
            }
            *(float4*)(Xs + r * XS_STRIDE + c4 * 4) = v;
        }
    }
    __syncthreads();

    const int tx = tid & 31;
    const int ty = tid >> 5;          // 0..7 -> rows ty*8 .. ty*8+7
    float4 acc[8][2];
    #pragma unroll
    for (int r = 0; r < 8; r++) {
        acc[r][0] = make_float4(0.f, 0.f, 0.f, 0.f);
        acc[r][1] = make_float4(0.f, 0.f, 0.f, 0.f);
    }

    #pragma unroll 4
    for (int k4 = 0; k4 < 16; k4++) {
        float4 av[8];
        #pragma unroll
        for (int r = 0; r < 8; r++)
            av[r] = *(const float4*)(Xs + (ty * 8 + r) * XS_STRIDE + k4 * 4);
        #pragma unroll
        for (int kk = 0; kk < 4; kk++) {
            const float4* wrow = (const float4*)(Ws + (k4 * 4 + kk) * 256);
            float4 b0 = wrow[tx];        // cols 4tx..4tx+3   (Ui/Uj half)
            float4 b1 = wrow[tx + 32];   // cols 128+4tx..    (Vi/Vj half)
            #pragma unroll
            for (int r = 0; r < 8; r++) {
                float a = (kk == 0) ? av[r].x : (kk == 1) ? av[r].y
                        : (kk == 2) ? av[r].z : av[r].w;
                FMA4(acc[r][0], a, b0);
                FMA4(acc[r][1], a, b1);
            }
        }
    }

    const int cx = tx & 15;   // float4 col index within the matrix
    if (tx < 16) {
        // matrix Ui -> su[+0], matrix Vi -> xvi
        #pragma unroll
        for (int r = 0; r < 8; r++) {
            int row = rowBase + ty * 8 + r;
            if (row < n) {
                ((float4*)(su  + (size_t)row * 128))[cx] = acc[r][0];
                ((float4*)(xvi + (size_t)row * 64 ))[cx] = acc[r][1];
            }
        }
    } else {
        float4 bu4 = ((const float4*)bu)[cx];
        float4 bv4 = ((const float4*)bv)[cx];
        #pragma unroll
        for (int r = 0; r < 8; r++) {
            int row = rowBase + ty * 8 + r;
            if (row < n) {
                float4 v1 = acc[r][0];
                v1.x += bu4.x; v1.y += bu4.y; v1.z += bu4.z; v1.w += bu4.w;
                ((float4*)(y + (size_t)row * 64))[cx] = v1;
                float4 v3 = acc[r][1];
                v3.x += bv4.x; v3.y += bv4.y; v3.z += bv4.z; v3.w += bv4.w;
                ((float4*)(su + (size_t)row * 128 + 64))[cx] = v3;
            }
        }
    }
}

// ================= per-node aggregation: 1 warp per node =================
__device__ __forceinline__ float4 sig_mul(float4 vi, float4 vj, float4 ui)
{
    float4 r;
    r.x = ui.x / (1.f + __expf(-(vi.x + vj.x)));
    r.y = ui.y / (1.f + __expf(-(vi.y + vj.y)));
    r.z = ui.z / (1.f + __expf(-(vi.z + vj.z)));
    r.w = ui.w / (1.f + __expf(-(vi.w + vj.w)));
    return r;
}

__global__ void agg_kernel(const float* __restrict__ xvi, const float* __restrict__ su,
                           float* __restrict__ y, float* __restrict__ stats, int n)
{
    __shared__ float s_sum[64], s_sum2[64];
    const int tid = threadIdx.x;
    if (tid < 64) { s_sum[tid] = 0.f; s_sum2[tid] = 0.f; }
    __syncthreads();

    const int warp = tid >> 5;
    const int lane = tid & 31;
    const int half = lane >> 4;
    const int l4   = lane & 15;
    const int node = blockIdx.x * 8 + warp;

    if (node < n) {
        float4 vi = ((const float4*)(xvi + (size_t)node * 64))[l4];
        float4 acc = make_float4(0.f, 0.f, 0.f, 0.f);
        const int p0 = g_off[node];
        const int p1 = g_off[node + 1];

        int pp = p0 + half;
        for (; pp + 2 < p1; pp += 4) {
            int bA = __ldg(g_srcSorted + pp);
            int bB = __ldg(g_srcSorted + pp + 2);
            const float4* sA = (const float4*)(su + (size_t)bA * 128);
            const float4* sB = (const float4*)(su + (size_t)bB * 128);
            float4 uiA = __ldg(sA + l4);
            float4 vjA = __ldg(sA + 16 + l4);
            float4 uiB = __ldg(sB + l4);
            float4 vjB = __ldg(sB + 16 + l4);
            float4 mA = sig_mul(vi, vjA, uiA);
            float4 mB = sig_mul(vi, vjB, uiB);
            acc.x += mA.x + mB.x;
            acc.y += mA.y + mB.y;
            acc.z += mA.z + mB.z;
            acc.w += mA.w + mB.w;
        }
        for (; pp < p1; pp += 2) {
            int b = __ldg(g_srcSorted + pp);
            const float4* sb = (const float4*)(su + (size_t)b * 128);
            float4 ui = __ldg(sb + l4);
            float4 vj = __ldg(sb + 16 + l4);
            float4 m = sig_mul(vi, vj, ui);
            acc.x += m.x; acc.y += m.y; acc.z += m.z; acc.w += m.w;
        }

        acc.x += __shfl_xor_sync(0xffffffffu, acc.x, 16);
        acc.y += __shfl_xor_sync(0xffffffffu, acc.y, 16);
        acc.z += __shfl_xor_sync(0xffffffffu, acc.z, 16);
        acc.w += __shfl_xor_sync(0xffffffffu, acc.w, 16);

        if (half == 0) {
            float4 base = ((const float4*)(y + (size_t)node * 64))[l4];
            acc.x += base.x; acc.y += base.y; acc.z += base.z; acc.w += base.w;
            ((float4*)(y + (size_t)node * 64))[l4] = acc;

            int c = l4 * 4;
            atomicAdd(&s_sum[c + 0], acc.x);  atomicAdd(&s_sum2[c + 0], acc.x * acc.x);
            atomicAdd(&s_sum[c + 1], acc.y);  atomicAdd(&s_sum2[c + 1], acc.y * acc.y);
            atomicAdd(&s_sum[c + 2], acc.z);  atomicAdd(&s_sum2[c + 2], acc.z * acc.z);
            atomicAdd(&s_sum[c + 3], acc.w);  atomicAdd(&s_sum2[c + 3], acc.w * acc.w);
        }
    }
    __syncthreads();
    if (tid < 64) {
        atomicAdd(stats + tid,      s_sum[tid]);
        atomicAdd(stats + 64 + tid, s_sum2[tid]);
    }
}

// ================= final: out = relu( BN2(y2) + x_in @ R ) =================
// 256 threads = 16 tx x 16 ty; 128-row tile; thread: 8 rows x 1 float4 col.
#define FINAL_SMEM (64*64*4 + 128*XS_STRIDE*4)

__global__ void __launch_bounds__(256)
final_kernel(const float* __restrict__ X, const float* __restrict__ R,
             const float* __restrict__ y2, const float* __restrict__ stats,
             const float* __restrict__ gamma, const float* __restrict__ beta,
             float* __restrict__ out, int n)
{
    extern __shared__ float smem[];
    float* Rs = smem;              // [64][64]
    float* Xs = smem + 64 * 64;    // [128][XS_STRIDE]
    const int tid = threadIdx.x;
    const int rowBase = blockIdx.x * 128;

    for (int i = tid; i < 1024; i += 256)
        ((float4*)Rs)[i] = ((const float4*)R)[i];
    for (int i = tid; i < 2048; i += 256) {
        int r = i >> 4, c4 = i & 15;
        int row = rowBase + r;
        float4 v = make_float4(0.f, 0.f, 0.f, 0.f);
        if (row < n) v = ((const float4*)X)[row * 16 + c4];
        *(float4*)(Xs + r * XS_STRIDE + c4 * 4) = v;
    }
    __syncthreads();

    const int tx = tid & 15;
    const int ty = tid >> 4;          // 0..15 -> rows ty*8..ty*8+7
    float4 acc[8];
    #pragma unroll
    for (int r = 0; r < 8; r++) acc[r] = make_float4(0.f, 0.f, 0.f, 0.f);

    #pragma unroll 4
    for (int k4 = 0; k4 < 16; k4++) {
        float4 av[8];
        #pragma unroll
        for (int r = 0; r < 8; r++)
            av[r] = *(const float4*)(Xs + (ty * 8 + r) * XS_STRIDE + k4 * 4);
        #pragma unroll
        for (int kk = 0; kk < 4; kk++) {
            float4 b = ((const float4*)(Rs + (k4 * 4 + kk) * 64))[tx];
            #pragma unroll
            for (int r = 0; r < 8; r++) {
                float a = (kk == 0) ? av[r].x : (kk == 1) ? av[r].y
                        : (kk == 2) ? av[r].z : av[r].w;
                FMA4(acc[r], a, b);
            }
        }
    }

    float fn = 1.f / (float)n;
    float scale[4], shift[4];
    #pragma unroll
    for (int j = 0; j < 4; j++) {
        int c = tx * 4 + j;
        float mean = stats[c] * fn;
        float var  = stats[64 + c] * fn - mean * mean;
        float sc = gamma[c] * rsqrtf(var + 1e-3f);
        scale[j] = sc;
        shift[j] = beta[c] - mean * sc;
    }

    #pragma unroll
    for (int r = 0; r < 8; r++) {
        int row = rowBase + ty * 8 + r;
        if (row < n) {
            float4 yv = ((const float4*)(y2 + (size_t)row * 64))[tx];
            float o0 = acc[r].x + yv.x * scale[0] + shift[0];
            float o1 = acc[r].y + yv.y * scale[1] + shift[1];
            float o2 = acc[r].z + yv.z * scale[2] + shift[2];
            float o3 = acc[r].w + yv.w * scale[3] + shift[3];
            float4 ov;
            ov.x = o0 > 0.f ? o0 : 0.f;
            ov.y = o1 > 0.f ? o1 : 0.f;
            ov.z = o2 > 0.f ? o2 : 0.f;
            ov.w = o3 > 0.f ? o3 : 0.f;
            ((float4*)(out + (size_t)row * 64))[tx] = ov;
        }
    }
}

// ================= host =================
extern "C" void kernel_launch(void* const* d_in, const int* in_sizes, int n_in,
                              void* d_out, int out_size)
{
    const float* u   = (const float*)d_in[0];
    const float* v   = (const float*)d_in[1];
    const int*   es  = (const int*)  d_in[2];
    const int*   ee  = (const int*)  d_in[3];
    const float* Ui1 = (const float*)d_in[4];
    const float* Uj1 = (const float*)d_in[5];
    const float* Vi1 = (const float*)d_in[6];
    const float* Vj1 = (const float*)d_in[7];
    const float* bu1 = (const float*)d_in[8];
    const float* bv1 = (const float*)d_in[9];
    const float* Ui2 = (const float*)d_in[10];
    const float* Uj2 = (const float*)d_in[11];
    const float* Vi2 = (const float*)d_in[12];
    const float* Vj2 = (const float*)d_in[13];
    const float* bu2 = (const float*)d_in[14];
    const float* bv2 = (const float*)d_in[15];
    const float* R   = (const float*)d_in[16];
    const float* gamma1 = (const float*)d_in[17];
    const float* beta1  = (const float*)d_in[18];
    const float* gamma2 = (const float*)d_in[19];
    const float* beta2  = (const float*)d_in[20];

    const int nU = in_sizes[0] / 64;
    const int nV = in_sizes[1] / 64;
    const int n  = nU + nV;
    const int nE = in_sizes[2];

    float *px, *psu, *pxvi, *py, *py2, *pst1, *pst2;
    int *pcnt;
    cudaGetSymbolAddress((void**)&px,   g_x);
    cudaGetSymbolAddress((void**)&psu,  g_su);
    cudaGetSymbolAddress((void**)&pxvi, g_xvi);
    cudaGetSymbolAddress((void**)&py,   g_y);
    cudaGetSymbolAddress((void**)&py2,  g_y2);
    cudaGetSymbolAddress((void**)&pst1, g_stats1);
    cudaGetSymbolAddress((void**)&pst2, g_stats2);
    cudaGetSymbolAddress((void**)&pcnt, g_cnt);

    cudaFuncSetAttribute(gemm4_kernel<false>, cudaFuncAttributeMaxDynamicSharedMemorySize, GEMM4_SMEM);
    cudaFuncSetAttribute(gemm4_kernel<true>,  cudaFuncAttributeMaxDynamicSharedMemorySize, GEMM4_SMEM);
    cudaFuncSetAttribute(final_kernel, cudaFuncAttributeMaxDynamicSharedMemorySize, FINAL_SMEM);

    cudaMemcpyAsync(px,                   u, (size_t)nU * 64 * sizeof(float), cudaMemcpyDeviceToDevice);
    cudaMemcpyAsync(px + (size_t)nU * 64, v, (size_t)nV * 64 * sizeof(float), cudaMemcpyDeviceToDevice);
    cudaMemsetAsync(pcnt, 0, (MAXN + 1) * sizeof(int));
    cudaMemsetAsync(pst1, 0, 2 * D * sizeof(float));
    cudaMemsetAsync(pst2, 0, 2 * D * sizeof(float));

    const int eb = (nE + 255) / 256;
    const int nb = (n + 255) / 256;
    const int gemmBlocks  = (n + 63) / 64;
    const int finalBlocks = (n + 127) / 128;
    const int aggBlocks   = (n + 7) / 8;

    hist_kernel<<<eb, 256>>>(ee, nE);
    scan_block_kernel<<<nb, 256>>>(n);
    scan_add_kernel<<<nb, 256>>>(n);

    // ---- stage 1 GEMM (profiled slot) ----
    gemm4_kernel<false><<<gemmBlocks, 256, GEMM4_SMEM>>>(px, Ui1, Uj1, Vi1, Vj1, bu1, bv1,
                                                         nullptr, nullptr, nullptr,
                                                         psu, py, pxvi, n);
    scatter_kernel<<<eb, 256>>>(es, ee, nE);
    agg_kernel<<<aggBlocks, 256>>>(pxvi, psu, py, pst1, n);

    // ---- stage 2 (BN1+ReLU fused into X load) ----
    gemm4_kernel<true><<<gemmBlocks, 256, GEMM4_SMEM>>>(py, Ui2, Uj2, Vi2, Vj2, bu2, bv2,
                                                        pst1, gamma1, beta1,
                                                        psu, py2, pxvi, n);
    agg_kernel<<<aggBlocks, 256>>>(pxvi, psu, py2, pst2, n);

    // ---- final: relu(BN2(y2) + x_in @ R) ----
    final_kernel<<<finalBlocks, 256, FINAL_SMEM>>>(px, R, py2, pst2, gamma2, beta2, (float*)d_out, n);
}

// round 7
// speedup vs baseline: 1.5358x; 1.5358x over previous
#include <cuda_runtime.h>
#include <math.h>

#define D 64
#define MAXN 100000
#define MAXE 1100000

// ---------------- static device scratch ----------------
__device__ float g_su [MAXN * 128];  // per-node: [0..63]=x@Ui, [64..127]=x@Vj+bv
__device__ float g_xvi[MAXN * D];
__device__ float g_y  [MAXN * D];    // stage1 output
__device__ float g_y2 [MAXN * D];    // stage2 output
__device__ float g_stats1[2 * D];
__device__ float g_stats2[2 * D];
// CSR (edges sorted by destination)
__device__ int g_cnt[MAXN + 1];
__device__ int g_off[MAXN + 1];
__device__ int g_cur[MAXN];
__device__ int g_srcSorted[MAXE];
__device__ int g_bsum[512];

#define FMA4(ACC, A, B) do { (ACC).x += (A)*(B).x; (ACC).y += (A)*(B).y; \
                             (ACC).z += (A)*(B).z; (ACC).w += (A)*(B).w; } while(0)

// ================= CSR build =================
__global__ void hist_kernel(const int* __restrict__ ee, int nE)
{
    int e = blockIdx.x * blockDim.x + threadIdx.x;
    if (e < nE) atomicAdd(&g_cnt[ee[e]], 1);
}

__global__ void scan_block_kernel(int n)
{
    __shared__ int sh[256];
    int tid = threadIdx.x;
    int i = blockIdx.x * 256 + tid;
    int v = (i < n) ? g_cnt[i] : 0;
    sh[tid] = v;
    __syncthreads();
    #pragma unroll
    for (int ofs = 1; ofs < 256; ofs <<= 1) {
        int x = (tid >= ofs) ? sh[tid - ofs] : 0;
        __syncthreads();
        sh[tid] += x;
        __syncthreads();
    }
    if (i < n) g_off[i] = sh[tid] - v;
    if (tid == 255) g_bsum[blockIdx.x] = sh[255];
}

__global__ void scan_add_kernel(int n)
{
    __shared__ int s_prefix;
    const int bid = blockIdx.x;
    if (threadIdx.x < 32) {
        int s = 0;
        for (int i = threadIdx.x; i < bid; i += 32) s += g_bsum[i];
        #pragma unroll
        for (int o = 16; o; o >>= 1) s += __shfl_down_sync(0xffffffffu, s, o);
        if (threadIdx.x == 0) s_prefix = s;
    }
    __syncthreads();
    int i = bid * 256 + threadIdx.x;
    if (i < n) {
        int o = g_off[i] + s_prefix;
        g_off[i] = o;
        g_cur[i] = o;
        if (i == n - 1) g_off[n] = o + g_cnt[i];
    }
}

__global__ void scatter_kernel(const int* __restrict__ es, const int* __restrict__ ee, int nE)
{
    int e = blockIdx.x * blockDim.x + threadIdx.x;
    if (e < nE) {
        int d = ee[e];
        int p = atomicAdd(&g_cur[d], 1);
        g_srcSorted[p] = es[e];
    }
}

// ================= fused 4-matrix GEMM: X[64-row tile] @ [Ui|Uj|Vi|Vj] =================
// R5 layout: 16 tx * 16 ty; thread tile 4 rows x 16 cols (float4 tx, tx+16, tx+32, tx+48)
// X is the primary input; rows >= nU come from Xv (direct concat read). For BN pass
// Xv = X and nU = n.
#define XS_STRIDE 68
#define GEMM4_SMEM (64*256*4 + 64*XS_STRIDE*4)

template<bool BN>
__global__ void gemm4_kernel(const float* __restrict__ X, const float* __restrict__ Xv, int nU,
                             const float* __restrict__ Ui, const float* __restrict__ Uj,
                             const float* __restrict__ Vi, const float* __restrict__ Vj,
                             const float* __restrict__ bu, const float* __restrict__ bv,
                             const float* __restrict__ stats, const float* __restrict__ gamma,
                             const float* __restrict__ beta,
                             float* __restrict__ su, float* __restrict__ y,
                             float* __restrict__ xvi,
                             int n)
{
    extern __shared__ float smem[];
    float* Ws = smem;              // [64][256]
    float* Xs = smem + 64 * 256;   // [64][XS_STRIDE]
    __shared__ float s_scale[64], s_shift[64];
    const int tid = threadIdx.x;
    const int rowBase = blockIdx.x * 64;

    if (BN) {
        if (tid < 64) {
            float fn = 1.f / (float)n;
            float mean = stats[tid] * fn;
            float var  = stats[64 + tid] * fn - mean * mean;
            float sc = gamma[tid] * rsqrtf(var + 1e-3f);
            s_scale[tid] = sc;
            s_shift[tid] = beta[tid] - mean * sc;
        }
        __syncthreads();
    }

    {
        const float* mats[4] = {Ui, Uj, Vi, Vj};
        #pragma unroll
        for (int m = 0; m < 4; m++) {
            const float4* src = (const float4*)mats[m];
            for (int i = tid; i < 1024; i += 256) {
                int k = i >> 4, j4 = i & 15;
                ((float4*)(Ws + k * 256 + m * 64))[j4] = src[k * 16 + j4];
            }
        }
        for (int i = tid; i < 1024; i += 256) {
            int r = i >> 4, c4 = i & 15;
            int row = rowBase + r;
            float4 v = make_float4(0.f, 0.f, 0.f, 0.f);
            if (row < n) {
                const float4* src = (row < nU) ? ((const float4*)X) + (size_t)row * 16
                                               : ((const float4*)Xv) + (size_t)(row - nU) * 16;
                v = src[c4];
            }
            if (BN) {
                int c = c4 * 4;
                v.x = fmaxf(v.x * s_scale[c+0] + s_shift[c+0], 0.f);
                v.y = fmaxf(v.y * s_scale[c+1] + s_shift[c+1], 0.f);
                v.z = fmaxf(v.z * s_scale[c+2] + s_shift[c+2], 0.f);
                v.w = fmaxf(v.w * s_scale[c+3] + s_shift[c+3], 0.f);
            }
            *(float4*)(Xs + r * XS_STRIDE + c4 * 4) = v;
        }
    }
    __syncthreads();

    const int tx = tid & 15;
    const int ty = tid >> 4;
    float4 acc[4][4];   // [row r][matrix c]
    #pragma unroll
    for (int r = 0; r < 4; r++)
        #pragma unroll
        for (int c = 0; c < 4; c++) acc[r][c] = make_float4(0.f, 0.f, 0.f, 0.f);

    #pragma unroll 8
    for (int k = 0; k < 64; k++) {
        float a0 = Xs[(ty * 4 + 0) * XS_STRIDE + k];
        float a1 = Xs[(ty * 4 + 1) * XS_STRIDE + k];
        float a2 = Xs[(ty * 4 + 2) * XS_STRIDE + k];
        float a3 = Xs[(ty * 4 + 3) * XS_STRIDE + k];
        const float4* wrow = (const float4*)(Ws + k * 256);
        float4 b0 = wrow[tx];        // matrix 0 (Ui), conflict-free
        float4 b1 = wrow[tx + 16];   // matrix 1 (Uj)
        float4 b2 = wrow[tx + 32];   // matrix 2 (Vi)
        float4 b3 = wrow[tx + 48];   // matrix 3 (Vj)
        FMA4(acc[0][0], a0, b0); FMA4(acc[0][1], a0, b1); FMA4(acc[0][2], a0, b2); FMA4(acc[0][3], a0, b3);
        FMA4(acc[1][0], a1, b0); FMA4(acc[1][1], a1, b1); FMA4(acc[1][2], a1, b2); FMA4(acc[1][3], a1, b3);
        FMA4(acc[2][0], a2, b0); FMA4(acc[2][1], a2, b1); FMA4(acc[2][2], a2, b2); FMA4(acc[2][3], a2, b3);
        FMA4(acc[3][0], a3, b0); FMA4(acc[3][1], a3, b1); FMA4(acc[3][2], a3, b2); FMA4(acc[3][3], a3, b3);
    }

    float4 bu4 = ((const float4*)bu)[tx];
    float4 bv4 = ((const float4*)bv)[tx];

    #pragma unroll
    for (int r = 0; r < 4; r++) {
        int row = rowBase + ty * 4 + r;
        if (row < n) {
            ((float4*)(su + (size_t)row * 128))[tx] = acc[r][0];
            float4 v1 = acc[r][1];
            v1.x += bu4.x; v1.y += bu4.y; v1.z += bu4.z; v1.w += bu4.w;
            ((float4*)(y + (size_t)row * 64))[tx] = v1;
            ((float4*)(xvi + (size_t)row * 64))[tx] = acc[r][2];
            float4 v3 = acc[r][3];
            v3.x += bv4.x; v3.y += bv4.y; v3.z += bv4.z; v3.w += bv4.w;
            ((float4*)(su + (size_t)row * 128 + 64))[tx] = v3;
        }
    }
}

// ================= per-node aggregation: 1 warp per node, 8 edges in flight =================
__device__ __forceinline__ float4 sig_mul(float4 vi, float4 vj, float4 ui)
{
    float4 r;
    r.x = ui.x / (1.f + __expf(-(vi.x + vj.x)));
    r.y = ui.y / (1.f + __expf(-(vi.y + vj.y)));
    r.z = ui.z / (1.f + __expf(-(vi.z + vj.z)));
    r.w = ui.w / (1.f + __expf(-(vi.w + vj.w)));
    return r;
}

__global__ void agg_kernel(const float* __restrict__ xvi, const float* __restrict__ su,
                           float* __restrict__ y, float* __restrict__ stats, int n)
{
    __shared__ float s_sum[64], s_sum2[64];
    const int tid = threadIdx.x;
    if (tid < 64) { s_sum[tid] = 0.f; s_sum2[tid] = 0.f; }
    __syncthreads();

    const int warp = tid >> 5;
    const int lane = tid & 31;
    const int half = lane >> 4;
    const int l4   = lane & 15;
    const int node = blockIdx.x * 8 + warp;

    if (node < n) {
        float4 vi = ((const float4*)(xvi + (size_t)node * 64))[l4];
        float4 acc = make_float4(0.f, 0.f, 0.f, 0.f);
        const int p0 = g_off[node];
        const int p1 = g_off[node + 1];

        int pp = p0 + half;
        // 8 edges per warp iteration (4 per half): all idx loads first, then 8 gathers
        for (; pp + 6 < p1; pp += 8) {
            int b0 = __ldg(g_srcSorted + pp);
            int b1 = __ldg(g_srcSorted + pp + 2);
            int b2 = __ldg(g_srcSorted + pp + 4);
            int b3 = __ldg(g_srcSorted + pp + 6);
            const float4* s0 = (const float4*)(su + (size_t)b0 * 128);
            const float4* s1 = (const float4*)(su + (size_t)b1 * 128);
            const float4* s2 = (const float4*)(su + (size_t)b2 * 128);
            const float4* s3 = (const float4*)(su + (size_t)b3 * 128);
            float4 ui0 = __ldg(s0 + l4);       float4 vj0 = __ldg(s0 + 16 + l4);
            float4 ui1 = __ldg(s1 + l4);       float4 vj1 = __ldg(s1 + 16 + l4);
            float4 ui2 = __ldg(s2 + l4);       float4 vj2 = __ldg(s2 + 16 + l4);
            float4 ui3 = __ldg(s3 + l4);       float4 vj3 = __ldg(s3 + 16 + l4);
            float4 m0 = sig_mul(vi, vj0, ui0);
            float4 m1 = sig_mul(vi, vj1, ui1);
            float4 m2 = sig_mul(vi, vj2, ui2);
            float4 m3 = sig_mul(vi, vj3, ui3);
            acc.x += (m0.x + m1.x) + (m2.x + m3.x);
            acc.y += (m0.y + m1.y) + (m2.y + m3.y);
            acc.z += (m0.z + m1.z) + (m2.z + m3.z);
            acc.w += (m0.w + m1.w) + (m2.w + m3.w);
        }
        for (; pp < p1; pp += 2) {
            int b = __ldg(g_srcSorted + pp);
            const float4* sb = (const float4*)(su + (size_t)b * 128);
            float4 ui = __ldg(sb + l4);
            float4 vj = __ldg(sb + 16 + l4);
            float4 m = sig_mul(vi, vj, ui);
            acc.x += m.x; acc.y += m.y; acc.z += m.z; acc.w += m.w;
        }

        acc.x += __shfl_xor_sync(0xffffffffu, acc.x, 16);
        acc.y += __shfl_xor_sync(0xffffffffu, acc.y, 16);
        acc.z += __shfl_xor_sync(0xffffffffu, acc.z, 16);
        acc.w += __shfl_xor_sync(0xffffffffu, acc.w, 16);

        if (half == 0) {
            float4 base = ((const float4*)(y + (size_t)node * 64))[l4];
            acc.x += base.x; acc.y += base.y; acc.z += base.z; acc.w += base.w;
            ((float4*)(y + (size_t)node * 64))[l4] = acc;

            int c = l4 * 4;
            atomicAdd(&s_sum[c + 0], acc.x);  atomicAdd(&s_sum2[c + 0], acc.x * acc.x);
            atomicAdd(&s_sum[c + 1], acc.y);  atomicAdd(&s_sum2[c + 1], acc.y * acc.y);
            atomicAdd(&s_sum[c + 2], acc.z);  atomicAdd(&s_sum2[c + 2], acc.z * acc.z);
            atomicAdd(&s_sum[c + 3], acc.w);  atomicAdd(&s_sum2[c + 3], acc.w * acc.w);
        }
    }
    __syncthreads();
    if (tid < 64) {
        atomicAdd(stats + tid,      s_sum[tid]);
        atomicAdd(stats + 64 + tid, s_sum2[tid]);
    }
}

// ================= final: out = relu( BN2(y2) + x_in @ R ) =================
// R5 layout (4 rows x 1 float4 col per thread), x_in read directly from u/v.
__global__ void final_kernel(const float* __restrict__ Xu, const float* __restrict__ Xv, int nU,
                             const float* __restrict__ R,
                             const float* __restrict__ y2, const float* __restrict__ stats,
                             const float* __restrict__ gamma, const float* __restrict__ beta,
                             float* __restrict__ out, int n)
{
    __shared__ float Rs[64 * 64];
    __shared__ float Xs[64 * XS_STRIDE];
    const int tid = threadIdx.x;
    const int rowBase = blockIdx.x * 64;

    for (int i = tid; i < 1024; i += 256)
        ((float4*)Rs)[i] = ((const float4*)R)[i];
    for (int i = tid; i < 1024; i += 256) {
        int r = i >> 4, c4 = i & 15;
        int row = rowBase + r;
        float4 v = make_float4(0.f, 0.f, 0.f, 0.f);
        if (row < n) {
            const float4* src = (row < nU) ? ((const float4*)Xu) + (size_t)row * 16
                                           : ((const float4*)Xv) + (size_t)(row - nU) * 16;
            v = src[c4];
        }
        *(float4*)(Xs + r * XS_STRIDE + c4 * 4) = v;
    }
    __syncthreads();

    const int tx = tid & 15;
    const int ty = tid >> 4;
    float4 acc[4];
    #pragma unroll
    for (int r = 0; r < 4; r++) acc[r] = make_float4(0.f, 0.f, 0.f, 0.f);

    #pragma unroll 8
    for (int k = 0; k < 64; k++) {
        float a0 = Xs[(ty * 4 + 0) * XS_STRIDE + k];
        float a1 = Xs[(ty * 4 + 1) * XS_STRIDE + k];
        float a2 = Xs[(ty * 4 + 2) * XS_STRIDE + k];
        float a3 = Xs[(ty * 4 + 3) * XS_STRIDE + k];
        float4 b = ((const float4*)(Rs + k * 64))[tx];
        FMA4(acc[0], a0, b);
        FMA4(acc[1], a1, b);
        FMA4(acc[2], a2, b);
        FMA4(acc[3], a3, b);
    }

    float fn = 1.f / (float)n;
    float scale[4], shift[4];
    #pragma unroll
    for (int j = 0; j < 4; j++) {
        int c = tx * 4 + j;
        float mean = stats[c] * fn;
        float var  = stats[64 + c] * fn - mean * mean;
        float sc = gamma[c] * rsqrtf(var + 1e-3f);
        scale[j] = sc;
        shift[j] = beta[c] - mean * sc;
    }

    #pragma unroll
    for (int r = 0; r < 4; r++) {
        int row = rowBase + ty * 4 + r;
        if (row < n) {
            float4 yv = ((const float4*)(y2 + (size_t)row * 64))[tx];
            float o0 = acc[r].x + yv.x * scale[0] + shift[0];
            float o1 = acc[r].y + yv.y * scale[1] + shift[1];
            float o2 = acc[r].z + yv.z * scale[2] + shift[2];
            float o3 = acc[r].w + yv.w * scale[3] + shift[3];
            float4 ov;
            ov.x = o0 > 0.f ? o0 : 0.f;
            ov.y = o1 > 0.f ? o1 : 0.f;
            ov.z = o2 > 0.f ? o2 : 0.f;
            ov.w = o3 > 0.f ? o3 : 0.f;
            ((float4*)(out + (size_t)row * 64))[tx] = ov;
        }
    }
}

// ================= host =================
extern "C" void kernel_launch(void* const* d_in, const int* in_sizes, int n_in,
                              void* d_out, int out_size)
{
    const float* u   = (const float*)d_in[0];
    const float* v   = (const float*)d_in[1];
    const int*   es  = (const int*)  d_in[2];
    const int*   ee  = (const int*)  d_in[3];
    const float* Ui1 = (const float*)d_in[4];
    const float* Uj1 = (const float*)d_in[5];
    const float* Vi1 = (const float*)d_in[6];
    const float* Vj1 = (const float*)d_in[7];
    const float* bu1 = (const float*)d_in[8];
    const float* bv1 = (const float*)d_in[9];
    const float* Ui2 = (const float*)d_in[10];
    const float* Uj2 = (const float*)d_in[11];
    const float* Vi2 = (const float*)d_in[12];
    const float* Vj2 = (const float*)d_in[13];
    const float* bu2 = (const float*)d_in[14];
    const float* bv2 = (const float*)d_in[15];
    const float* R   = (const float*)d_in[16];
    const float* gamma1 = (const float*)d_in[17];
    const float* beta1  = (const float*)d_in[18];
    const float* gamma2 = (const float*)d_in[19];
    const float* beta2  = (const float*)d_in[20];

    const int nU = in_sizes[0] / 64;
    const int nV = in_sizes[1] / 64;
    const int n  = nU + nV;
    const int nE = in_sizes[2];

    float *psu, *pxvi, *py, *py2, *pst1, *pst2;
    int *pcnt;
    cudaGetSymbolAddress((void**)&psu,  g_su);
    cudaGetSymbolAddress((void**)&pxvi, g_xvi);
    cudaGetSymbolAddress((void**)&py,   g_y);
    cudaGetSymbolAddress((void**)&py2,  g_y2);
    cudaGetSymbolAddress((void**)&pst1, g_stats1);
    cudaGetSymbolAddress((void**)&pst2, g_stats2);
    cudaGetSymbolAddress((void**)&pcnt, g_cnt);

    cudaFuncSetAttribute(gemm4_kernel<false>, cudaFuncAttributeMaxDynamicSharedMemorySize, GEMM4_SMEM);
    cudaFuncSetAttribute(gemm4_kernel<true>,  cudaFuncAttributeMaxDynamicSharedMemorySize, GEMM4_SMEM);

    cudaMemsetAsync(pcnt, 0, (MAXN + 1) * sizeof(int));
    cudaMemsetAsync(pst1, 0, 2 * D * sizeof(float));
    cudaMemsetAsync(pst2, 0, 2 * D * sizeof(float));

    const int eb = (nE + 255) / 256;
    const int nb = (n + 255) / 256;
    const int gemmBlocks = (n + 63) / 64;
    const int aggBlocks  = (n + 7) / 8;

    hist_kernel<<<eb, 256>>>(ee, nE);
    scan_block_kernel<<<nb, 256>>>(n);
    scan_add_kernel<<<nb, 256>>>(n);

    // ---- stage 1 GEMM (profiled slot #4) ----
    gemm4_kernel<false><<<gemmBlocks, 256, GEMM4_SMEM>>>(u, v, nU,
                                                         Ui1, Uj1, Vi1, Vj1, bu1, bv1,
                                                         nullptr, nullptr, nullptr,
                                                         psu, py, pxvi, n);
    scatter_kernel<<<eb, 256>>>(es, ee, nE);
    agg_kernel<<<aggBlocks, 256>>>(pxvi, psu, py, pst1, n);

    // ---- stage 2 (BN1+ReLU fused into X load) ----
    gemm4_kernel<true><<<gemmBlocks, 256, GEMM4_SMEM>>>(py, py, n,
                                                        Ui2, Uj2, Vi2, Vj2, bu2, bv2,
                                                        pst1, gamma1, beta1,
                                                        psu, py2, pxvi, n);
    agg_kernel<<<aggBlocks, 256>>>(pxvi, psu, py2, pst2, n);

    // ---- final: relu(BN2(y2) + x_in @ R) ----
    final_kernel<<<gemmBlocks, 256>>>(u, v, nU, R, py2, pst2, gamma2, beta2, (float*)d_out, n);
}

// round 8
// speedup vs baseline: 1.7233x; 1.1221x over previous
#include <cuda_runtime.h>
#include <cuda_fp16.h>
#include <math.h>

#define D 64
#define MAXN 100000
#define MAXE 1100000

// ---------------- static device scratch ----------------
// packed per-node record: 64 x half2(ui[c], vj[c]+bv[c])  = 256 B
__device__ unsigned g_suh[MAXN * 64];
__device__ float g_xvi[MAXN * D];
__device__ float g_y  [MAXN * D];    // stage1 output
__device__ float g_y2 [MAXN * D];    // stage2 output
__device__ float g_stats1[2 * D];
__device__ float g_stats2[2 * D];
// CSR (edges sorted by destination)
__device__ int g_cnt[MAXN + 1];
__device__ int g_off[MAXN + 1];
__device__ int g_cur[MAXN];
__device__ int g_srcSorted[MAXE];
__device__ int g_bsum[512];

#define FMA4(ACC, A, B) do { (ACC).x += (A)*(B).x; (ACC).y += (A)*(B).y; \
                             (ACC).z += (A)*(B).z; (ACC).w += (A)*(B).w; } while(0)

// ================= CSR build =================
__global__ void hist_kernel(const int* __restrict__ ee, int nE)
{
    int e = blockIdx.x * blockDim.x + threadIdx.x;
    if (e < nE) atomicAdd(&g_cnt[ee[e]], 1);
}

__global__ void scan_block_kernel(int n)
{
    __shared__ int sh[256];
    int tid = threadIdx.x;
    int i = blockIdx.x * 256 + tid;
    int v = (i < n) ? g_cnt[i] : 0;
    sh[tid] = v;
    __syncthreads();
    #pragma unroll
    for (int ofs = 1; ofs < 256; ofs <<= 1) {
        int x = (tid >= ofs) ? sh[tid - ofs] : 0;
        __syncthreads();
        sh[tid] += x;
        __syncthreads();
    }
    if (i < n) g_off[i] = sh[tid] - v;
    if (tid == 255) g_bsum[blockIdx.x] = sh[255];
}

__global__ void scan_add_kernel(int n)
{
    __shared__ int s_prefix;
    const int bid = blockIdx.x;
    if (threadIdx.x < 32) {
        int s = 0;
        for (int i = threadIdx.x; i < bid; i += 32) s += g_bsum[i];
        #pragma unroll
        for (int o = 16; o; o >>= 1) s += __shfl_down_sync(0xffffffffu, s, o);
        if (threadIdx.x == 0) s_prefix = s;
    }
    __syncthreads();
    int i = bid * 256 + threadIdx.x;
    if (i < n) {
        int o = g_off[i] + s_prefix;
        g_off[i] = o;
        g_cur[i] = o;
        if (i == n - 1) g_off[n] = o + g_cnt[i];
    }
}

__global__ void scatter_kernel(const int* __restrict__ es, const int* __restrict__ ee, int nE)
{
    int e = blockIdx.x * blockDim.x + threadIdx.x;
    if (e < nE) {
        int d = ee[e];
        int p = atomicAdd(&g_cur[d], 1);
        g_srcSorted[p] = es[e];
    }
}

// ================= fused 4-matrix GEMM: X[64-row tile] @ [Ui|Uj|Vi|Vj] =================
#define XS_STRIDE 68
#define GEMM4_SMEM (64*256*4 + 64*XS_STRIDE*4)

__device__ __forceinline__ unsigned pack_h2(float a, float b)
{
    __half2 h = __floats2half2_rn(a, b);
    return *reinterpret_cast<unsigned*>(&h);
}

template<bool BN>
__global__ void gemm4_kernel(const float* __restrict__ X, const float* __restrict__ Xv, int nU,
                             const float* __restrict__ Ui, const float* __restrict__ Uj,
                             const float* __restrict__ Vi, const float* __restrict__ Vj,
                             const float* __restrict__ bu, const float* __restrict__ bv,
                             const float* __restrict__ stats, const float* __restrict__ gamma,
                             const float* __restrict__ beta,
                             unsigned* __restrict__ suh, float* __restrict__ y,
                             float* __restrict__ xvi,
                             int n)
{
    extern __shared__ float smem[];
    float* Ws = smem;              // [64][256]
    float* Xs = smem + 64 * 256;   // [64][XS_STRIDE]
    __shared__ float s_scale[64], s_shift[64];
    const int tid = threadIdx.x;
    const int rowBase = blockIdx.x * 64;

    if (BN) {
        if (tid < 64) {
            float fn = 1.f / (float)n;
            float mean = stats[tid] * fn;
            float var  = stats[64 + tid] * fn - mean * mean;
            float sc = gamma[tid] * rsqrtf(var + 1e-3f);
            s_scale[tid] = sc;
            s_shift[tid] = beta[tid] - mean * sc;
        }
        __syncthreads();
    }

    {
        const float* mats[4] = {Ui, Uj, Vi, Vj};
        #pragma unroll
        for (int m = 0; m < 4; m++) {
            const float4* src = (const float4*)mats[m];
            for (int i = tid; i < 1024; i += 256) {
                int k = i >> 4, j4 = i & 15;
                ((float4*)(Ws + k * 256 + m * 64))[j4] = src[k * 16 + j4];
            }
        }
        for (int i = tid; i < 1024; i += 256) {
            int r = i >> 4, c4 = i & 15;
            int row = rowBase + r;
            float4 v = make_float4(0.f, 0.f, 0.f, 0.f);
            if (row < n) {
                const float4* src = (row < nU) ? ((const float4*)X) + (size_t)row * 16
                                               : ((const float4*)Xv) + (size_t)(row - nU) * 16;
                v = src[c4];
            }
            if (BN) {
                int c = c4 * 4;
                v.x = fmaxf(v.x * s_scale[c+0] + s_shift[c+0], 0.f);
                v.y = fmaxf(v.y * s_scale[c+1] + s_shift[c+1], 0.f);
                v.z = fmaxf(v.z * s_scale[c+2] + s_shift[c+2], 0.f);
                v.w = fmaxf(v.w * s_scale[c+3] + s_shift[c+3], 0.f);
            }
            *(float4*)(Xs + r * XS_STRIDE + c4 * 4) = v;
        }
    }
    __syncthreads();

    const int tx = tid & 15;
    const int ty = tid >> 4;
    float4 acc[4][4];   // [row r][matrix c]
    #pragma unroll
    for (int r = 0; r < 4; r++)
        #pragma unroll
        for (int c = 0; c < 4; c++) acc[r][c] = make_float4(0.f, 0.f, 0.f, 0.f);

    #pragma unroll 8
    for (int k = 0; k < 64; k++) {
        float a0 = Xs[(ty * 4 + 0) * XS_STRIDE + k];
        float a1 = Xs[(ty * 4 + 1) * XS_STRIDE + k];
        float a2 = Xs[(ty * 4 + 2) * XS_STRIDE + k];
        float a3 = Xs[(ty * 4 + 3) * XS_STRIDE + k];
        const float4* wrow = (const float4*)(Ws + k * 256);
        float4 b0 = wrow[tx];        // Ui
        float4 b1 = wrow[tx + 16];   // Uj
        float4 b2 = wrow[tx + 32];   // Vi
        float4 b3 = wrow[tx + 48];   // Vj
        FMA4(acc[0][0], a0, b0); FMA4(acc[0][1], a0, b1); FMA4(acc[0][2], a0, b2); FMA4(acc[0][3], a0, b3);
        FMA4(acc[1][0], a1, b0); FMA4(acc[1][1], a1, b1); FMA4(acc[1][2], a1, b2); FMA4(acc[1][3], a1, b3);
        FMA4(acc[2][0], a2, b0); FMA4(acc[2][1], a2, b1); FMA4(acc[2][2], a2, b2); FMA4(acc[2][3], a2, b3);
        FMA4(acc[3][0], a3, b0); FMA4(acc[3][1], a3, b1); FMA4(acc[3][2], a3, b2); FMA4(acc[3][3], a3, b3);
    }

    float4 bu4 = ((const float4*)bu)[tx];
    float4 bv4 = ((const float4*)bv)[tx];

    #pragma unroll
    for (int r = 0; r < 4; r++) {
        int row = rowBase + ty * 4 + r;
        if (row < n) {
            // y = x@Uj + bu
            float4 v1 = acc[r][1];
            v1.x += bu4.x; v1.y += bu4.y; v1.z += bu4.z; v1.w += bu4.w;
            ((float4*)(y + (size_t)row * 64))[tx] = v1;
            // xvi
            ((float4*)(xvi + (size_t)row * 64))[tx] = acc[r][2];
            // packed record: half2(ui[c], vj[c]+bv[c]) for cols 4tx..4tx+3
            float4 ui4 = acc[r][0];
            float4 vj4 = acc[r][3];
            vj4.x += bv4.x; vj4.y += bv4.y; vj4.z += bv4.z; vj4.w += bv4.w;
            uint4 pk;
            pk.x = pack_h2(ui4.x, vj4.x);
            pk.y = pack_h2(ui4.y, vj4.y);
            pk.z = pack_h2(ui4.z, vj4.z);
            pk.w = pack_h2(ui4.w, vj4.w);
            ((uint4*)(suh + (size_t)row * 64))[tx] = pk;
        }
    }
}

// ================= per-node aggregation: 1 warp per node, fp16 packed gathers =================
__device__ __forceinline__ void edge_acc(float4& acc, const float4& vi, uint4 pk)
{
    float2 f0 = __half22float2(*reinterpret_cast<__half2*>(&pk.x));
    float2 f1 = __half22float2(*reinterpret_cast<__half2*>(&pk.y));
    float2 f2 = __half22float2(*reinterpret_cast<__half2*>(&pk.z));
    float2 f3 = __half22float2(*reinterpret_cast<__half2*>(&pk.w));
    acc.x += f0.x / (1.f + __expf(-(vi.x + f0.y)));
    acc.y += f1.x / (1.f + __expf(-(vi.y + f1.y)));
    acc.z += f2.x / (1.f + __expf(-(vi.z + f2.y)));
    acc.w += f3.x / (1.f + __expf(-(vi.w + f3.y)));
}

__global__ void agg_kernel(const float* __restrict__ xvi, const unsigned* __restrict__ suh,
                           float* __restrict__ y, float* __restrict__ stats, int n)
{
    __shared__ float s_sum[64], s_sum2[64];
    const int tid = threadIdx.x;
    if (tid < 64) { s_sum[tid] = 0.f; s_sum2[tid] = 0.f; }
    __syncthreads();

    const int warp = tid >> 5;
    const int lane = tid & 31;
    const int half = lane >> 4;
    const int l4   = lane & 15;
    const int node = blockIdx.x * 8 + warp;

    if (node < n) {
        float4 vi = ((const float4*)(xvi + (size_t)node * 64))[l4];
        float4 acc = make_float4(0.f, 0.f, 0.f, 0.f);
        const int p0 = g_off[node];
        const int p1 = g_off[node + 1];

        int pp = p0 + half;
        // 8 edges per warp iteration (4 per half): 4 idx + 4 LDG.128 in flight
        for (; pp + 6 < p1; pp += 8) {
            int b0 = __ldg(g_srcSorted + pp);
            int b1 = __ldg(g_srcSorted + pp + 2);
            int b2 = __ldg(g_srcSorted + pp + 4);
            int b3 = __ldg(g_srcSorted + pp + 6);
            uint4 k0 = __ldg((const uint4*)(suh + (size_t)b0 * 64) + l4);
            uint4 k1 = __ldg((const uint4*)(suh + (size_t)b1 * 64) + l4);
            uint4 k2 = __ldg((const uint4*)(suh + (size_t)b2 * 64) + l4);
            uint4 k3 = __ldg((const uint4*)(suh + (size_t)b3 * 64) + l4);
            edge_acc(acc, vi, k0);
            edge_acc(acc, vi, k1);
            edge_acc(acc, vi, k2);
            edge_acc(acc, vi, k3);
        }
        for (; pp < p1; pp += 2) {
            int b = __ldg(g_srcSorted + pp);
            uint4 k = __ldg((const uint4*)(suh + (size_t)b * 64) + l4);
            edge_acc(acc, vi, k);
        }

        acc.x += __shfl_xor_sync(0xffffffffu, acc.x, 16);
        acc.y += __shfl_xor_sync(0xffffffffu, acc.y, 16);
        acc.z += __shfl_xor_sync(0xffffffffu, acc.z, 16);
        acc.w += __shfl_xor_sync(0xffffffffu, acc.w, 16);

        if (half == 0) {
            float4 base = ((const float4*)(y + (size_t)node * 64))[l4];
            acc.x += base.x; acc.y += base.y; acc.z += base.z; acc.w += base.w;
            ((float4*)(y + (size_t)node * 64))[l4] = acc;

            int c = l4 * 4;
            atomicAdd(&s_sum[c + 0], acc.x);  atomicAdd(&s_sum2[c + 0], acc.x * acc.x);
            atomicAdd(&s_sum[c + 1], acc.y);  atomicAdd(&s_sum2[c + 1], acc.y * acc.y);
            atomicAdd(&s_sum[c + 2], acc.z);  atomicAdd(&s_sum2[c + 2], acc.z * acc.z);
            atomicAdd(&s_sum[c + 3], acc.w);  atomicAdd(&s_sum2[c + 3], acc.w * acc.w);
        }
    }
    __syncthreads();
    if (tid < 64) {
        atomicAdd(stats + tid,      s_sum[tid]);
        atomicAdd(stats + 64 + tid, s_sum2[tid]);
    }
}

// ================= final: out = relu( BN2(y2) + x_in @ R ) =================
__global__ void final_kernel(const float* __restrict__ Xu, const float* __restrict__ Xv, int nU,
                             const float* __restrict__ R,
                             const float* __restrict__ y2, const float* __restrict__ stats,
                             const float* __restrict__ gamma, const float* __restrict__ beta,
                             float* __restrict__ out, int n)
{
    __shared__ float Rs[64 * 64];
    __shared__ float Xs[64 * XS_STRIDE];
    const int tid = threadIdx.x;
    const int rowBase = blockIdx.x * 64;

    for (int i = tid; i < 1024; i += 256)
        ((float4*)Rs)[i] = ((const float4*)R)[i];
    for (int i = tid; i < 1024; i += 256) {
        int r = i >> 4, c4 = i & 15;
        int row = rowBase + r;
        float4 v = make_float4(0.f, 0.f, 0.f, 0.f);
        if (row < n) {
            const float4* src = (row < nU) ? ((const float4*)Xu) + (size_t)row * 16
                                           : ((const float4*)Xv) + (size_t)(row - nU) * 16;
            v = src[c4];
        }
        *(float4*)(Xs + r * XS_STRIDE + c4 * 4) = v;
    }
    __syncthreads();

    const int tx = tid & 15;
    const int ty = tid >> 4;
    float4 acc[4];
    #pragma unroll
    for (int r = 0; r < 4; r++) acc[r] = make_float4(0.f, 0.f, 0.f, 0.f);

    #pragma unroll 8
    for (int k = 0; k < 64; k++) {
        float a0 = Xs[(ty * 4 + 0) * XS_STRIDE + k];
        float a1 = Xs[(ty * 4 + 1) * XS_STRIDE + k];
        float a2 = Xs[(ty * 4 + 2) * XS_STRIDE + k];
        float a3 = Xs[(ty * 4 + 3) * XS_STRIDE + k];
        float4 b = ((const float4*)(Rs + k * 64))[tx];
        FMA4(acc[0], a0, b);
        FMA4(acc[1], a1, b);
        FMA4(acc[2], a2, b);
        FMA4(acc[3], a3, b);
    }

    float fn = 1.f / (float)n;
    float scale[4], shift[4];
    #pragma unroll
    for (int j = 0; j < 4; j++) {
        int c = tx * 4 + j;
        float mean = stats[c] * fn;
        float var  = stats[64 + c] * fn - mean * mean;
        float sc = gamma[c] * rsqrtf(var + 1e-3f);
        scale[j] = sc;
        shift[j] = beta[c] - mean * sc;
    }

    #pragma unroll
    for (int r = 0; r < 4; r++) {
        int row = rowBase + ty * 4 + r;
        if (row < n) {
            float4 yv = ((const float4*)(y2 + (size_t)row * 64))[tx];
            float o0 = acc[r].x + yv.x * scale[0] + shift[0];
            float o1 = acc[r].y + yv.y * scale[1] + shift[1];
            float o2 = acc[r].z + yv.z * scale[2] + shift[2];
            float o3 = acc[r].w + yv.w * scale[3] + shift[3];
            float4 ov;
            ov.x = o0 > 0.f ? o0 : 0.f;
            ov.y = o1 > 0.f ? o1 : 0.f;
            ov.z = o2 > 0.f ? o2 : 0.f;
            ov.w = o3 > 0.f ? o3 : 0.f;
            ((float4*)(out + (size_t)row * 64))[tx] = ov;
        }
    }
}

// ================= host =================
extern "C" void kernel_launch(void* const* d_in, const int* in_sizes, int n_in,
                              void* d_out, int out_size)
{
    const float* u   = (const float*)d_in[0];
    const float* v   = (const float*)d_in[1];
    const int*   es  = (const int*)  d_in[2];
    const int*   ee  = (const int*)  d_in[3];
    const float* Ui1 = (const float*)d_in[4];
    const float* Uj1 = (const float*)d_in[5];
    const float* Vi1 = (const float*)d_in[6];
    const float* Vj1 = (const float*)d_in[7];
    const float* bu1 = (const float*)d_in[8];
    const float* bv1 = (const float*)d_in[9];
    const float* Ui2 = (const float*)d_in[10];
    const float* Uj2 = (const float*)d_in[11];
    const float* Vi2 = (const float*)d_in[12];
    const float* Vj2 = (const float*)d_in[13];
    const float* bu2 = (const float*)d_in[14];
    const float* bv2 = (const float*)d_in[15];
    const float* R   = (const float*)d_in[16];
    const float* gamma1 = (const float*)d_in[17];
    const float* beta1  = (const float*)d_in[18];
    const float* gamma2 = (const float*)d_in[19];
    const float* beta2  = (const float*)d_in[20];

    const int nU = in_sizes[0] / 64;
    const int nV = in_sizes[1] / 64;
    const int n  = nU + nV;
    const int nE = in_sizes[2];

    float *pxvi, *py, *py2, *pst1, *pst2;
    unsigned *psuh;
    int *pcnt;
    cudaGetSymbolAddress((void**)&psuh, g_suh);
    cudaGetSymbolAddress((void**)&pxvi, g_xvi);
    cudaGetSymbolAddress((void**)&py,   g_y);
    cudaGetSymbolAddress((void**)&py2,  g_y2);
    cudaGetSymbolAddress((void**)&pst1, g_stats1);
    cudaGetSymbolAddress((void**)&pst2, g_stats2);
    cudaGetSymbolAddress((void**)&pcnt, g_cnt);

    cudaFuncSetAttribute(gemm4_kernel<false>, cudaFuncAttributeMaxDynamicSharedMemorySize, GEMM4_SMEM);
    cudaFuncSetAttribute(gemm4_kernel<true>,  cudaFuncAttributeMaxDynamicSharedMemorySize, GEMM4_SMEM);

    cudaMemsetAsync(pcnt, 0, (MAXN + 1) * sizeof(int));
    cudaMemsetAsync(pst1, 0, 2 * D * sizeof(float));
    cudaMemsetAsync(pst2, 0, 2 * D * sizeof(float));

    const int eb = (nE + 255) / 256;
    const int nb = (n + 255) / 256;
    const int gemmBlocks = (n + 63) / 64;
    const int aggBlocks  = (n + 7) / 8;

    hist_kernel<<<eb, 256>>>(ee, nE);
    scan_block_kernel<<<nb, 256>>>(n);
    scan_add_kernel<<<nb, 256>>>(n);

    // ---- stage 1 GEMM (profiled slot #4) ----
    gemm4_kernel<false><<<gemmBlocks, 256, GEMM4_SMEM>>>(u, v, nU,
                                                         Ui1, Uj1, Vi1, Vj1, bu1, bv1,
                                                         nullptr, nullptr, nullptr,
                                                         psuh, py, pxvi, n);
    scatter_kernel<<<eb, 256>>>(es, ee, nE);
    agg_kernel<<<aggBlocks, 256>>>(pxvi, psuh, py, pst1, n);

    // ---- stage 2 (BN1+ReLU fused into X load) ----
    gemm4_kernel<true><<<gemmBlocks, 256, GEMM4_SMEM>>>(py, py, n,
                                                        Ui2, Uj2, Vi2, Vj2, bu2, bv2,
                                                        pst1, gamma1, beta1,
                                                        psuh, py2, pxvi, n);
    agg_kernel<<<aggBlocks, 256>>>(pxvi, psuh, py2, pst2, n);

    // ---- final: relu(BN2(y2) + x_in @ R) ----
    final_kernel<<<gemmBlocks, 256>>>(u, v, nU, R, py2, pst2, gamma2, beta2, (float*)d_out, n);
}

// round 9
// speedup vs baseline: 2.1231x; 1.2320x over previous
#include <cuda_runtime.h>
#include <cuda_fp16.h>
#include <math.h>

#define D 64
#define MAXN 100000
#define MAXE 1100000

// ---------------- static device scratch ----------------
// packed per-node record: 64 x half2(ui[c], vj[c]+bv[c])  = 256 B
__device__ unsigned g_suh[MAXN * 64];
__device__ float g_xvi[MAXN * D];
__device__ float g_y  [MAXN * D];    // stage1 output
__device__ float g_y2 [MAXN * D];    // stage2 output
__device__ float g_stats1[2 * D];
__device__ float g_stats2[2 * D];
// CSR (edges sorted by destination)
__device__ int g_cnt[MAXN + 1];
__device__ int g_off[MAXN + 1];
__device__ int g_cur[MAXN];
__device__ int g_srcSorted[MAXE];
__device__ int g_bsum[512];

#define FMA4(ACC, A, B) do { (ACC).x += (A)*(B).x; (ACC).y += (A)*(B).y; \
                             (ACC).z += (A)*(B).z; (ACC).w += (A)*(B).w; } while(0)

// ================= CSR build =================
__global__ void hist_kernel(const int* __restrict__ ee, int nE)
{
    int e = blockIdx.x * blockDim.x + threadIdx.x;
    if (e < nE) atomicAdd(&g_cnt[ee[e]], 1);
}

__global__ void scan_block_kernel(int n)
{
    __shared__ int sh[256];
    int tid = threadIdx.x;
    int i = blockIdx.x * 256 + tid;
    int v = (i < n) ? g_cnt[i] : 0;
    sh[tid] = v;
    __syncthreads();
    #pragma unroll
    for (int ofs = 1; ofs < 256; ofs <<= 1) {
        int x = (tid >= ofs) ? sh[tid - ofs] : 0;
        __syncthreads();
        sh[tid] += x;
        __syncthreads();
    }
    if (i < n) g_off[i] = sh[tid] - v;
    if (tid == 255) g_bsum[blockIdx.x] = sh[255];
}

__global__ void scan_add_kernel(int n)
{
    __shared__ int s_prefix;
    const int bid = blockIdx.x;
    if (threadIdx.x < 32) {
        int s = 0;
        for (int i = threadIdx.x; i < bid; i += 32) s += g_bsum[i];
        #pragma unroll
        for (int o = 16; o; o >>= 1) s += __shfl_down_sync(0xffffffffu, s, o);
        if (threadIdx.x == 0) s_prefix = s;
    }
    __syncthreads();
    int i = bid * 256 + threadIdx.x;
    if (i < n) {
        int o = g_off[i] + s_prefix;
        g_off[i] = o;
        g_cur[i] = o;
        if (i == n - 1) g_off[n] = o + g_cnt[i];
    }
}

__global__ void scatter_kernel(const int* __restrict__ es, const int* __restrict__ ee, int nE)
{
    int e = blockIdx.x * blockDim.x + threadIdx.x;
    if (e < nE) {
        int d = ee[e];
        int p = atomicAdd(&g_cur[d], 1);
        g_srcSorted[p] = es[e];
    }
}

// ================= tf32 mma helpers =================
__device__ __forceinline__ unsigned f2tf32(float x)
{
    unsigned r;
    asm("cvt.rna.tf32.f32 %0, %1;" : "=r"(r) : "f"(x));
    return r;
}

__device__ __forceinline__ void mma_tf32(float* d, unsigned a0, unsigned a1,
                                         unsigned a2, unsigned a3,
                                         unsigned b0, unsigned b1)
{
    asm volatile(
        "mma.sync.aligned.m16n8k8.row.col.f32.tf32.tf32.f32 "
        "{%0,%1,%2,%3}, {%4,%5,%6,%7}, {%8,%9}, {%0,%1,%2,%3};"
        : "+f"(d[0]), "+f"(d[1]), "+f"(d[2]), "+f"(d[3])
        : "r"(a0), "r"(a1), "r"(a2), "r"(a3), "r"(b0), "r"(b1));
}

__device__ __forceinline__ unsigned pack_h2(float a, float b)
{
    __half2 h = __floats2half2_rn(a, b);
    return *reinterpret_cast<unsigned*>(&h);
}

// ================= fused 4-matrix GEMM via tf32 tensor cores =================
// Block: 64 rows x 256 cols (all 4 matrices), K=64, 8 warps.
// Warp w owns cols [w*8, w*8+8) of EACH matrix (n-tiles at m*64 + w*8).
#define WS_STRIDE 264
#define AS_STRIDE 68
#define GEMM4_SMEM (64*WS_STRIDE*4 + 64*AS_STRIDE*4)

template<bool BN>
__global__ void __launch_bounds__(256, 2)
gemm4_kernel(const float* __restrict__ X, const float* __restrict__ Xv, int nU,
             const float* __restrict__ Ui, const float* __restrict__ Uj,
             const float* __restrict__ Vi, const float* __restrict__ Vj,
             const float* __restrict__ bu, const float* __restrict__ bv,
             const float* __restrict__ stats, const float* __restrict__ gamma,
             const float* __restrict__ beta,
             unsigned* __restrict__ suh, float* __restrict__ y,
             float* __restrict__ xvi,
             int n)
{
    extern __shared__ float smem[];
    unsigned* Ws = (unsigned*)smem;                       // [64][264] tf32 bits
    unsigned* As = (unsigned*)(smem + 64 * WS_STRIDE);    // [64][68]  tf32 bits
    __shared__ float s_scale[64], s_shift[64];
    const int tid = threadIdx.x;
    const int rowBase = blockIdx.x * 64;

    if (BN) {
        if (tid < 64) {
            float fn = 1.f / (float)n;
            float mean = stats[tid] * fn;
            float var  = stats[64 + tid] * fn - mean * mean;
            float sc = gamma[tid] * rsqrtf(var + 1e-3f);
            s_scale[tid] = sc;
            s_shift[tid] = beta[tid] - mean * sc;
        }
        __syncthreads();
    }

    // stage W (4 matrices side by side) as tf32
    {
        const float* mats[4] = {Ui, Uj, Vi, Vj};
        #pragma unroll
        for (int m = 0; m < 4; m++) {
            const float4* src = (const float4*)mats[m];
            for (int i = tid; i < 1024; i += 256) {
                int k = i >> 4, j4 = i & 15;
                float4 w = src[i];
                uint4 p;
                p.x = f2tf32(w.x); p.y = f2tf32(w.y);
                p.z = f2tf32(w.z); p.w = f2tf32(w.w);
                *(uint4*)(Ws + k * WS_STRIDE + m * 64 + j4 * 4) = p;
            }
        }
        // stage X (with optional BN+ReLU) as tf32
        for (int i = tid; i < 1024; i += 256) {
            int r = i >> 4, c4 = i & 15;
            int row = rowBase + r;
            float4 v = make_float4(0.f, 0.f, 0.f, 0.f);
            if (row < n) {
                const float4* src = (row < nU) ? ((const float4*)X) + (size_t)row * 16
                                               : ((const float4*)Xv) + (size_t)(row - nU) * 16;
                v = src[c4];
            }
            if (BN) {
                int c = c4 * 4;
                v.x = fmaxf(v.x * s_scale[c+0] + s_shift[c+0], 0.f);
                v.y = fmaxf(v.y * s_scale[c+1] + s_shift[c+1], 0.f);
                v.z = fmaxf(v.z * s_scale[c+2] + s_shift[c+2], 0.f);
                v.w = fmaxf(v.w * s_scale[c+3] + s_shift[c+3], 0.f);
            }
            uint4 p;
            p.x = f2tf32(v.x); p.y = f2tf32(v.y);
            p.z = f2tf32(v.z); p.w = f2tf32(v.w);
            *(uint4*)(As + r * AS_STRIDE + c4 * 4) = p;
        }
    }
    __syncthreads();

    const int warp = tid >> 5;
    const int lane = tid & 31;
    const int g = lane >> 2;      // groupID 0..7
    const int t = lane & 3;       // threadID_in_group 0..3
    const int nbase = warp * 8;   // col within each matrix

    float acc[4][4][4];           // [mtile][ntile(=matrix)][c0..c3]
    #pragma unroll
    for (int mt = 0; mt < 4; mt++)
        #pragma unroll
        for (int nt = 0; nt < 4; nt++)
            #pragma unroll
            for (int c = 0; c < 4; c++) acc[mt][nt][c] = 0.f;

    #pragma unroll
    for (int k0 = 0; k0 < 64; k0 += 8) {
        unsigned b[4][2];
        #pragma unroll
        for (int nt = 0; nt < 4; nt++) {
            int cb = nt * 64 + nbase;
            b[nt][0] = Ws[(k0 + t)     * WS_STRIDE + cb + g];
            b[nt][1] = Ws[(k0 + t + 4) * WS_STRIDE + cb + g];
        }
        #pragma unroll
        for (int mt = 0; mt < 4; mt++) {
            int r0 = mt * 16;
            unsigned a0 = As[(r0 + g)     * AS_STRIDE + k0 + t];
            unsigned a1 = As[(r0 + g + 8) * AS_STRIDE + k0 + t];
            unsigned a2 = As[(r0 + g)     * AS_STRIDE + k0 + t + 4];
            unsigned a3 = As[(r0 + g + 8) * AS_STRIDE + k0 + t + 4];
            #pragma unroll
            for (int nt = 0; nt < 4; nt++)
                mma_tf32(acc[mt][nt], a0, a1, a2, a3, b[nt][0], b[nt][1]);
        }
    }

    // epilogue: thread owns cols c, c+1 (c = nbase + 2t) of each matrix,
    // rows mt*16 + g and mt*16 + g + 8.
    const int c = nbase + 2 * t;
    float2 bu2 = *(const float2*)(bu + c);
    float2 bv2 = *(const float2*)(bv + c);

    #pragma unroll
    for (int mt = 0; mt < 4; mt++) {
        #pragma unroll
        for (int h = 0; h < 2; h++) {
            int row = rowBase + mt * 16 + g + 8 * h;
            if (row < n) {
                float u0  = acc[mt][0][2*h],   u1  = acc[mt][0][2*h+1];
                float j0  = acc[mt][1][2*h] + bu2.x, j1 = acc[mt][1][2*h+1] + bu2.y;
                float vi0 = acc[mt][2][2*h],   vi1 = acc[mt][2][2*h+1];
                float vj0 = acc[mt][3][2*h] + bv2.x, vj1 = acc[mt][3][2*h+1] + bv2.y;
                *(float2*)(y   + (size_t)row * 64 + c) = make_float2(j0, j1);
                *(float2*)(xvi + (size_t)row * 64 + c) = make_float2(vi0, vi1);
                uint2 pk;
                pk.x = pack_h2(u0, vj0);
                pk.y = pack_h2(u1, vj1);
                *(uint2*)(suh + (size_t)row * 64 + c) = pk;
            }
        }
    }
}

// ================= per-node aggregation: 1 warp per node, fp16 packed gathers =================
__device__ __forceinline__ void edge_acc(float4& acc, const float4& vi, uint4 pk)
{
    float2 f0 = __half22float2(*reinterpret_cast<__half2*>(&pk.x));
    float2 f1 = __half22float2(*reinterpret_cast<__half2*>(&pk.y));
    float2 f2 = __half22float2(*reinterpret_cast<__half2*>(&pk.z));
    float2 f3 = __half22float2(*reinterpret_cast<__half2*>(&pk.w));
    acc.x += f0.x / (1.f + __expf(-(vi.x + f0.y)));
    acc.y += f1.x / (1.f + __expf(-(vi.y + f1.y)));
    acc.z += f2.x / (1.f + __expf(-(vi.z + f2.y)));
    acc.w += f3.x / (1.f + __expf(-(vi.w + f3.y)));
}

__global__ void agg_kernel(const float* __restrict__ xvi, const unsigned* __restrict__ suh,
                           float* __restrict__ y, float* __restrict__ stats, int n)
{
    __shared__ float s_sum[64], s_sum2[64];
    const int tid = threadIdx.x;
    if (tid < 64) { s_sum[tid] = 0.f; s_sum2[tid] = 0.f; }
    __syncthreads();

    const int warp = tid >> 5;
    const int lane = tid & 31;
    const int half = lane >> 4;
    const int l4   = lane & 15;
    const int node = blockIdx.x * 8 + warp;

    if (node < n) {
        float4 vi = ((const float4*)(xvi + (size_t)node * 64))[l4];
        float4 acc = make_float4(0.f, 0.f, 0.f, 0.f);
        const int p0 = g_off[node];
        const int p1 = g_off[node + 1];

        int pp = p0 + half;
        for (; pp + 6 < p1; pp += 8) {
            int b0 = __ldg(g_srcSorted + pp);
            int b1 = __ldg(g_srcSorted + pp + 2);
            int b2 = __ldg(g_srcSorted + pp + 4);
            int b3 = __ldg(g_srcSorted + pp + 6);
            uint4 k0 = __ldg((const uint4*)(suh + (size_t)b0 * 64) + l4);
            uint4 k1 = __ldg((const uint4*)(suh + (size_t)b1 * 64) + l4);
            uint4 k2 = __ldg((const uint4*)(suh + (size_t)b2 * 64) + l4);
            uint4 k3 = __ldg((const uint4*)(suh + (size_t)b3 * 64) + l4);
            edge_acc(acc, vi, k0);
            edge_acc(acc, vi, k1);
            edge_acc(acc, vi, k2);
            edge_acc(acc, vi, k3);
        }
        for (; pp < p1; pp += 2) {
            int b = __ldg(g_srcSorted + pp);
            uint4 k = __ldg((const uint4*)(suh + (size_t)b * 64) + l4);
            edge_acc(acc, vi, k);
        }

        acc.x += __shfl_xor_sync(0xffffffffu, acc.x, 16);
        acc.y += __shfl_xor_sync(0xffffffffu, acc.y, 16);
        acc.z += __shfl_xor_sync(0xffffffffu, acc.z, 16);
        acc.w += __shfl_xor_sync(0xffffffffu, acc.w, 16);

        if (half == 0) {
            float4 base = ((const float4*)(y + (size_t)node * 64))[l4];
            acc.x += base.x; acc.y += base.y; acc.z += base.z; acc.w += base.w;
            ((float4*)(y + (size_t)node * 64))[l4] = acc;

            int c = l4 * 4;
            atomicAdd(&s_sum[c + 0], acc.x);  atomicAdd(&s_sum2[c + 0], acc.x * acc.x);
            atomicAdd(&s_sum[c + 1], acc.y);  atomicAdd(&s_sum2[c + 1], acc.y * acc.y);
            atomicAdd(&s_sum[c + 2], acc.z);  atomicAdd(&s_sum2[c + 2], acc.z * acc.z);
            atomicAdd(&s_sum[c + 3], acc.w);  atomicAdd(&s_sum2[c + 3], acc.w * acc.w);
        }
    }
    __syncthreads();
    if (tid < 64) {
        atomicAdd(stats + tid,      s_sum[tid]);
        atomicAdd(stats + 64 + tid, s_sum2[tid]);
    }
}

// ================= final: out = relu( BN2(y2) + x_in @ R ) [fp32 FFMA] =================
#define XS_STRIDE 68

__global__ void final_kernel(const float* __restrict__ Xu, const float* __restrict__ Xv, int nU,
                             const float* __restrict__ R,
                             const float* __restrict__ y2, const float* __restrict__ stats,
                             const float* __restrict__ gamma, const float* __restrict__ beta,
                             float* __restrict__ out, int n)
{
    __shared__ float Rs[64 * 64];
    __shared__ float Xs[64 * XS_STRIDE];
    const int tid = threadIdx.x;
    const int rowBase = blockIdx.x * 64;

    for (int i = tid; i < 1024; i += 256)
        ((float4*)Rs)[i] = ((const float4*)R)[i];
    for (int i = tid; i < 1024; i += 256) {
        int r = i >> 4, c4 = i & 15;
        int row = rowBase + r;
        float4 v = make_float4(0.f, 0.f, 0.f, 0.f);
        if (row < n) {
            const float4* src = (row < nU) ? ((const float4*)Xu) + (size_t)row * 16
                                           : ((const float4*)Xv) + (size_t)(row - nU) * 16;
            v = src[c4];
        }
        *(float4*)(Xs + r * XS_STRIDE + c4 * 4) = v;
    }
    __syncthreads();

    const int tx = tid & 15;
    const int ty = tid >> 4;
    float4 acc[4];
    #pragma unroll
    for (int r = 0; r < 4; r++) acc[r] = make_float4(0.f, 0.f, 0.f, 0.f);

    #pragma unroll 8
    for (int k = 0; k < 64; k++) {
        float a0 = Xs[(ty * 4 + 0) * XS_STRIDE + k];
        float a1 = Xs[(ty * 4 + 1) * XS_STRIDE + k];
        float a2 = Xs[(ty * 4 + 2) * XS_STRIDE + k];
        float a3 = Xs[(ty * 4 + 3) * XS_STRIDE + k];
        float4 b = ((const float4*)(Rs + k * 64))[tx];
        FMA4(acc[0], a0, b);
        FMA4(acc[1], a1, b);
        FMA4(acc[2], a2, b);
        FMA4(acc[3], a3, b);
    }

    float fn = 1.f / (float)n;
    float scale[4], shift[4];
    #pragma unroll
    for (int j = 0; j < 4; j++) {
        int c = tx * 4 + j;
        float mean = stats[c] * fn;
        float var  = stats[64 + c] * fn - mean * mean;
        float sc = gamma[c] * rsqrtf(var + 1e-3f);
        scale[j] = sc;
        shift[j] = beta[c] - mean * sc;
    }

    #pragma unroll
    for (int r = 0; r < 4; r++) {
        int row = rowBase + ty * 4 + r;
        if (row < n) {
            float4 yv = ((const float4*)(y2 + (size_t)row * 64))[tx];
            float o0 = acc[r].x + yv.x * scale[0] + shift[0];
            float o1 = acc[r].y + yv.y * scale[1] + shift[1];
            float o2 = acc[r].z + yv.z * scale[2] + shift[2];
            float o3 = acc[r].w + yv.w * scale[3] + shift[3];
            float4 ov;
            ov.x = o0 > 0.f ? o0 : 0.f;
            ov.y = o1 > 0.f ? o1 : 0.f;
            ov.z = o2 > 0.f ? o2 : 0.f;
            ov.w = o3 > 0.f ? o3 : 0.f;
            ((float4*)(out + (size_t)row * 64))[tx] = ov;
        }
    }
}

// ================= host =================
extern "C" void kernel_launch(void* const* d_in, const int* in_sizes, int n_in,
                              void* d_out, int out_size)
{
    const float* u   = (const float*)d_in[0];
    const float* v   = (const float*)d_in[1];
    const int*   es  = (const int*)  d_in[2];
    const int*   ee  = (const int*)  d_in[3];
    const float* Ui1 = (const float*)d_in[4];
    const float* Uj1 = (const float*)d_in[5];
    const float* Vi1 = (const float*)d_in[6];
    const float* Vj1 = (const float*)d_in[7];
    const float* bu1 = (const float*)d_in[8];
    const float* bv1 = (const float*)d_in[9];
    const float* Ui2 = (const float*)d_in[10];
    const float* Uj2 = (const float*)d_in[11];
    const float* Vi2 = (const float*)d_in[12];
    const float* Vj2 = (const float*)d_in[13];
    const float* bu2 = (const float*)d_in[14];
    const float* bv2 = (const float*)d_in[15];
    const float* R   = (const float*)d_in[16];
    const float* gamma1 = (const float*)d_in[17];
    const float* beta1  = (const float*)d_in[18];
    const float* gamma2 = (const float*)d_in[19];
    const float* beta2  = (const float*)d_in[20];

    const int nU = in_sizes[0] / 64;
    const int nV = in_sizes[1] / 64;
    const int n  = nU + nV;
    const int nE = in_sizes[2];

    float *pxvi, *py, *py2, *pst1, *pst2;
    unsigned *psuh;
    int *pcnt;
    cudaGetSymbolAddress((void**)&psuh, g_suh);
    cudaGetSymbolAddress((void**)&pxvi, g_xvi);
    cudaGetSymbolAddress((void**)&py,   g_y);
    cudaGetSymbolAddress((void**)&py2,  g_y2);
    cudaGetSymbolAddress((void**)&pst1, g_stats1);
    cudaGetSymbolAddress((void**)&pst2, g_stats2);
    cudaGetSymbolAddress((void**)&pcnt, g_cnt);

    cudaFuncSetAttribute(gemm4_kernel<false>, cudaFuncAttributeMaxDynamicSharedMemorySize, GEMM4_SMEM);
    cudaFuncSetAttribute(gemm4_kernel<true>,  cudaFuncAttributeMaxDynamicSharedMemorySize, GEMM4_SMEM);

    cudaMemsetAsync(pcnt, 0, (MAXN + 1) * sizeof(int));
    cudaMemsetAsync(pst1, 0, 2 * D * sizeof(float));
    cudaMemsetAsync(pst2, 0, 2 * D * sizeof(float));

    const int eb = (nE + 255) / 256;
    const int nb = (n + 255) / 256;
    const int gemmBlocks = (n + 63) / 64;
    const int aggBlocks  = (n + 7) / 8;

    hist_kernel<<<eb, 256>>>(ee, nE);
    scan_block_kernel<<<nb, 256>>>(n);
    scan_add_kernel<<<nb, 256>>>(n);

    // ---- stage 1 GEMM (profiled slot #4) ----
    gemm4_kernel<false><<<gemmBlocks, 256, GEMM4_SMEM>>>(u, v, nU,
                                                         Ui1, Uj1, Vi1, Vj1, bu1, bv1,
                                                         nullptr, nullptr, nullptr,
                                                         psuh, py, pxvi, n);
    scatter_kernel<<<eb, 256>>>(es, ee, nE);
    agg_kernel<<<aggBlocks, 256>>>(pxvi, psuh, py, pst1, n);

    // ---- stage 2 (BN1+ReLU fused into X load) ----
    gemm4_kernel<true><<<gemmBlocks, 256, GEMM4_SMEM>>>(py, py, n,
                                                        Ui2, Uj2, Vi2, Vj2, bu2, bv2,
                                                        pst1, gamma1, beta1,
                                                        psuh, py2, pxvi, n);
    agg_kernel<<<aggBlocks, 256>>>(pxvi, psuh, py2, pst2, n);

    // ---- final: relu(BN2(y2) + x_in @ R) ----
    final_kernel<<<gemmBlocks, 256>>>(u, v, nU, R, py2, pst2, gamma2, beta2, (float*)d_out, n);
}

// round 10
// speedup vs baseline: 2.2527x; 1.0611x over previous
#include <cuda_runtime.h>
#include <cuda_fp16.h>
#include <math.h>

#define D 64
#define MAXN 100000
#define MAXE 1100000

// ---------------- static device scratch ----------------
// packed per-node record: 64 x half2(ui[c], vj[c]+bv[c])  = 256 B
__device__ unsigned g_suh[MAXN * 64];
__device__ float g_xvi[MAXN * D];
__device__ float g_y  [MAXN * D];    // stage1 output
__device__ float g_y2 [MAXN * D];    // stage2 output
__device__ float g_stats1[2 * D];
__device__ float g_stats2[2 * D];
// CSR (edges sorted by destination)
__device__ int g_cnt[MAXN + 1];
__device__ int g_off[MAXN + 1];
__device__ int g_cur[MAXN];
__device__ int g_srcSorted[MAXE];
__device__ int g_bsum[512];

// ================= CSR build =================
__global__ void hist_kernel(const int* __restrict__ ee, int nE)
{
    int e = blockIdx.x * blockDim.x + threadIdx.x;
    if (e < nE) atomicAdd(&g_cnt[ee[e]], 1);
}

__global__ void scan_block_kernel(int n)
{
    __shared__ int sh[256];
    int tid = threadIdx.x;
    int i = blockIdx.x * 256 + tid;
    int v = (i < n) ? g_cnt[i] : 0;
    sh[tid] = v;
    __syncthreads();
    #pragma unroll
    for (int ofs = 1; ofs < 256; ofs <<= 1) {
        int x = (tid >= ofs) ? sh[tid - ofs] : 0;
        __syncthreads();
        sh[tid] += x;
        __syncthreads();
    }
    if (i < n) g_off[i] = sh[tid] - v;
    if (tid == 255) g_bsum[blockIdx.x] = sh[255];
}

__global__ void scan_add_kernel(int n)
{
    __shared__ int s_prefix;
    const int bid = blockIdx.x;
    // fold stats zeroing into this kernel (block 0)
    if (bid == 0 && threadIdx.x < 128) {
        g_stats1[threadIdx.x] = 0.f;
        g_stats2[threadIdx.x] = 0.f;
    }
    if (threadIdx.x < 32) {
        int s = 0;
        for (int i = threadIdx.x; i < bid; i += 32) s += g_bsum[i];
        #pragma unroll
        for (int o = 16; o; o >>= 1) s += __shfl_down_sync(0xffffffffu, s, o);
        if (threadIdx.x == 0) s_prefix = s;
    }
    __syncthreads();
    int i = bid * 256 + threadIdx.x;
    if (i < n) {
        int o = g_off[i] + s_prefix;
        g_off[i] = o;
        g_cur[i] = o;
        if (i == n - 1) g_off[n] = o + g_cnt[i];
    }
}

__global__ void scatter_kernel(const int* __restrict__ es, const int* __restrict__ ee, int nE)
{
    int e = blockIdx.x * blockDim.x + threadIdx.x;
    if (e < nE) {
        int d = ee[e];
        int p = atomicAdd(&g_cur[d], 1);
        g_srcSorted[p] = es[e];
    }
}

// ================= tf32 mma helpers =================
__device__ __forceinline__ unsigned f2tf32(float x)
{
    unsigned r;
    asm("cvt.rna.tf32.f32 %0, %1;" : "=r"(r) : "f"(x));
    return r;
}

__device__ __forceinline__ void mma_tf32(float* d, unsigned a0, unsigned a1,
                                         unsigned a2, unsigned a3,
                                         unsigned b0, unsigned b1)
{
    asm volatile(
        "mma.sync.aligned.m16n8k8.row.col.f32.tf32.tf32.f32 "
        "{%0,%1,%2,%3}, {%4,%5,%6,%7}, {%8,%9}, {%0,%1,%2,%3};"
        : "+f"(d[0]), "+f"(d[1]), "+f"(d[2]), "+f"(d[3])
        : "r"(a0), "r"(a1), "r"(a2), "r"(a3), "r"(b0), "r"(b1));
}

__device__ __forceinline__ unsigned pack_h2(float a, float b)
{
    __half2 h = __floats2half2_rn(a, b);
    return *reinterpret_cast<unsigned*>(&h);
}

// ================= fused 4-matrix GEMM via tf32 tensor cores =================
// Block: 128 rows (two 64-row subtiles, acc reused) x 256 cols, K=64, 8 warps.
#define WS_STRIDE 264
#define AS_STRIDE 68
#define GEMM4_SMEM (64*WS_STRIDE*4 + 64*AS_STRIDE*4)

template<bool BN>
__global__ void __launch_bounds__(256, 2)
gemm4_kernel(const float* __restrict__ X, const float* __restrict__ Xv, int nU,
             const float* __restrict__ Ui, const float* __restrict__ Uj,
             const float* __restrict__ Vi, const float* __restrict__ Vj,
             const float* __restrict__ bu, const float* __restrict__ bv,
             const float* __restrict__ stats, const float* __restrict__ gamma,
             const float* __restrict__ beta,
             unsigned* __restrict__ suh, float* __restrict__ y,
             float* __restrict__ xvi,
             int n)
{
    extern __shared__ float smem[];
    unsigned* Ws = (unsigned*)smem;                       // [64][264] tf32 bits
    unsigned* As = (unsigned*)(smem + 64 * WS_STRIDE);    // [64][68]  tf32 bits
    __shared__ float s_scale[64], s_shift[64];
    const int tid = threadIdx.x;
    const int rowBase0 = blockIdx.x * 128;

    if (BN) {
        if (tid < 64) {
            float fn = 1.f / (float)n;
            float mean = stats[tid] * fn;
            float var  = stats[64 + tid] * fn - mean * mean;
            float sc = gamma[tid] * rsqrtf(var + 1e-3f);
            s_scale[tid] = sc;
            s_shift[tid] = beta[tid] - mean * sc;
        }
        __syncthreads();
    }

    // stage W (4 matrices side by side) once per block
    {
        const float* mats[4] = {Ui, Uj, Vi, Vj};
        #pragma unroll
        for (int m = 0; m < 4; m++) {
            const float4* src = (const float4*)mats[m];
            for (int i = tid; i < 1024; i += 256) {
                int k = i >> 4, j4 = i & 15;
                float4 w = src[i];
                uint4 p;
                p.x = f2tf32(w.x); p.y = f2tf32(w.y);
                p.z = f2tf32(w.z); p.w = f2tf32(w.w);
                *(uint4*)(Ws + k * WS_STRIDE + m * 64 + j4 * 4) = p;
            }
        }
    }

    const int warp = tid >> 5;
    const int lane = tid & 31;
    const int g = lane >> 2;
    const int t = lane & 3;
    const int nbase = warp * 8;
    const int c = nbase + 2 * t;
    float2 bu2 = *(const float2*)(bu + c);
    float2 bv2 = *(const float2*)(bv + c);

    #pragma unroll 1
    for (int st = 0; st < 2; st++) {
        const int rowBase = rowBase0 + st * 64;
        if (rowBase >= n) break;

        // stage X subtile (with optional BN+ReLU) as tf32
        for (int i = tid; i < 1024; i += 256) {
            int r = i >> 4, c4 = i & 15;
            int row = rowBase + r;
            float4 v = make_float4(0.f, 0.f, 0.f, 0.f);
            if (row < n) {
                const float4* src = (row < nU) ? ((const float4*)X) + (size_t)row * 16
                                               : ((const float4*)Xv) + (size_t)(row - nU) * 16;
                v = src[c4];
            }
            if (BN) {
                int cc = c4 * 4;
                v.x = fmaxf(v.x * s_scale[cc+0] + s_shift[cc+0], 0.f);
                v.y = fmaxf(v.y * s_scale[cc+1] + s_shift[cc+1], 0.f);
                v.z = fmaxf(v.z * s_scale[cc+2] + s_shift[cc+2], 0.f);
                v.w = fmaxf(v.w * s_scale[cc+3] + s_shift[cc+3], 0.f);
            }
            uint4 p;
            p.x = f2tf32(v.x); p.y = f2tf32(v.y);
            p.z = f2tf32(v.z); p.w = f2tf32(v.w);
            *(uint4*)(As + r * AS_STRIDE + c4 * 4) = p;
        }
        __syncthreads();

        float acc[4][4][4];   // [mtile][matrix][c0..c3]
        #pragma unroll
        for (int mt = 0; mt < 4; mt++)
            #pragma unroll
            for (int nt = 0; nt < 4; nt++)
                #pragma unroll
                for (int cc = 0; cc < 4; cc++) acc[mt][nt][cc] = 0.f;

        #pragma unroll
        for (int k0 = 0; k0 < 64; k0 += 8) {
            unsigned b[4][2];
            #pragma unroll
            for (int nt = 0; nt < 4; nt++) {
                int cb = nt * 64 + nbase;
                b[nt][0] = Ws[(k0 + t)     * WS_STRIDE + cb + g];
                b[nt][1] = Ws[(k0 + t + 4) * WS_STRIDE + cb + g];
            }
            #pragma unroll
            for (int mt = 0; mt < 4; mt++) {
                int r0 = mt * 16;
                unsigned a0 = As[(r0 + g)     * AS_STRIDE + k0 + t];
                unsigned a1 = As[(r0 + g + 8) * AS_STRIDE + k0 + t];
                unsigned a2 = As[(r0 + g)     * AS_STRIDE + k0 + t + 4];
                unsigned a3 = As[(r0 + g + 8) * AS_STRIDE + k0 + t + 4];
                #pragma unroll
                for (int nt = 0; nt < 4; nt++)
                    mma_tf32(acc[mt][nt], a0, a1, a2, a3, b[nt][0], b[nt][1]);
            }
        }

        // epilogue: thread owns cols c, c+1 of each matrix; rows mt*16+g, +8
        #pragma unroll
        for (int mt = 0; mt < 4; mt++) {
            #pragma unroll
            for (int h = 0; h < 2; h++) {
                int row = rowBase + mt * 16 + g + 8 * h;
                if (row < n) {
                    float u0  = acc[mt][0][2*h],   u1  = acc[mt][0][2*h+1];
                    float j0  = acc[mt][1][2*h] + bu2.x, j1 = acc[mt][1][2*h+1] + bu2.y;
                    float vi0 = acc[mt][2][2*h],   vi1 = acc[mt][2][2*h+1];
                    float vj0 = acc[mt][3][2*h] + bv2.x, vj1 = acc[mt][3][2*h+1] + bv2.y;
                    *(float2*)(y   + (size_t)row * 64 + c) = make_float2(j0, j1);
                    *(float2*)(xvi + (size_t)row * 64 + c) = make_float2(vi0, vi1);
                    uint2 pk;
                    pk.x = pack_h2(u0, vj0);
                    pk.y = pack_h2(u1, vj1);
                    *(uint2*)(suh + (size_t)row * 64 + c) = pk;
                }
            }
        }
        __syncthreads();   // protect As before next subtile overwrite
    }
}

// ================= per-node aggregation: 4 nodes per warp (sequential) =================
__device__ __forceinline__ void edge_acc(float4& acc, const float4& vi, uint4 pk)
{
    float2 f0 = __half22float2(*reinterpret_cast<__half2*>(&pk.x));
    float2 f1 = __half22float2(*reinterpret_cast<__half2*>(&pk.y));
    float2 f2 = __half22float2(*reinterpret_cast<__half2*>(&pk.z));
    float2 f3 = __half22float2(*reinterpret_cast<__half2*>(&pk.w));
    acc.x += f0.x / (1.f + __expf(-(vi.x + f0.y)));
    acc.y += f1.x / (1.f + __expf(-(vi.y + f1.y)));
    acc.z += f2.x / (1.f + __expf(-(vi.z + f2.y)));
    acc.w += f3.x / (1.f + __expf(-(vi.w + f3.y)));
}

__global__ void agg_kernel(const float* __restrict__ xvi, const unsigned* __restrict__ suh,
                           float* __restrict__ y, float* __restrict__ stats, int n)
{
    __shared__ float s_sum[64], s_sum2[64];
    const int tid = threadIdx.x;
    if (tid < 64) { s_sum[tid] = 0.f; s_sum2[tid] = 0.f; }
    __syncthreads();

    const int warp = tid >> 5;
    const int lane = tid & 31;
    const int half = lane >> 4;
    const int l4   = lane & 15;
    const int nodeBase = blockIdx.x * 32 + warp * 4;

    float4 st1 = make_float4(0.f, 0.f, 0.f, 0.f);
    float4 st2 = make_float4(0.f, 0.f, 0.f, 0.f);

    #pragma unroll 1
    for (int q = 0; q < 4; q++) {
        const int node = nodeBase + q;
        if (node >= n) break;

        float4 vi = ((const float4*)(xvi + (size_t)node * 64))[l4];
        float4 acc = make_float4(0.f, 0.f, 0.f, 0.f);
        const int p0 = g_off[node];
        const int p1 = g_off[node + 1];

        int pp = p0 + half;
        for (; pp + 6 < p1; pp += 8) {
            int b0 = __ldg(g_srcSorted + pp);
            int b1 = __ldg(g_srcSorted + pp + 2);
            int b2 = __ldg(g_srcSorted + pp + 4);
            int b3 = __ldg(g_srcSorted + pp + 6);
            uint4 k0 = __ldg((const uint4*)(suh + (size_t)b0 * 64) + l4);
            uint4 k1 = __ldg((const uint4*)(suh + (size_t)b1 * 64) + l4);
            uint4 k2 = __ldg((const uint4*)(suh + (size_t)b2 * 64) + l4);
            uint4 k3 = __ldg((const uint4*)(suh + (size_t)b3 * 64) + l4);
            edge_acc(acc, vi, k0);
            edge_acc(acc, vi, k1);
            edge_acc(acc, vi, k2);
            edge_acc(acc, vi, k3);
        }
        for (; pp < p1; pp += 2) {
            int b = __ldg(g_srcSorted + pp);
            uint4 k = __ldg((const uint4*)(suh + (size_t)b * 64) + l4);
            edge_acc(acc, vi, k);
        }

        acc.x += __shfl_xor_sync(0xffffffffu, acc.x, 16);
        acc.y += __shfl_xor_sync(0xffffffffu, acc.y, 16);
        acc.z += __shfl_xor_sync(0xffffffffu, acc.z, 16);
        acc.w += __shfl_xor_sync(0xffffffffu, acc.w, 16);

        if (half == 0) {
            float4 base = ((const float4*)(y + (size_t)node * 64))[l4];
            acc.x += base.x; acc.y += base.y; acc.z += base.z; acc.w += base.w;
            ((float4*)(y + (size_t)node * 64))[l4] = acc;
            st1.x += acc.x; st1.y += acc.y; st1.z += acc.z; st1.w += acc.w;
            st2.x += acc.x * acc.x; st2.y += acc.y * acc.y;
            st2.z += acc.z * acc.z; st2.w += acc.w * acc.w;
        }
    }

    if (half == 0) {
        int cc = l4 * 4;
        atomicAdd(&s_sum[cc + 0], st1.x);  atomicAdd(&s_sum2[cc + 0], st2.x);
        atomicAdd(&s_sum[cc + 1], st1.y);  atomicAdd(&s_sum2[cc + 1], st2.y);
        atomicAdd(&s_sum[cc + 2], st1.z);  atomicAdd(&s_sum2[cc + 2], st2.z);
        atomicAdd(&s_sum[cc + 3], st1.w);  atomicAdd(&s_sum2[cc + 3], st2.w);
    }
    __syncthreads();
    if (tid < 64) {
        atomicAdd(stats + tid,      s_sum[tid]);
        atomicAdd(stats + 64 + tid, s_sum2[tid]);
    }
}

// ================= final: out = relu( BN2(y2) + x_in @ R ) [fp32 FFMA] =================
#define XS_STRIDE 68

__global__ void final_kernel(const float* __restrict__ Xu, const float* __restrict__ Xv, int nU,
                             const float* __restrict__ R,
                             const float* __restrict__ y2, const float* __restrict__ stats,
                             const float* __restrict__ gamma, const float* __restrict__ beta,
                             float* __restrict__ out, int n)
{
    __shared__ float Rs[64 * 64];
    __shared__ float Xs[64 * XS_STRIDE];
    const int tid = threadIdx.x;
    const int rowBase = blockIdx.x * 64;

    for (int i = tid; i < 1024; i += 256)
        ((float4*)Rs)[i] = ((const float4*)R)[i];
    for (int i = tid; i < 1024; i += 256) {
        int r = i >> 4, c4 = i & 15;
        int row = rowBase + r;
        float4 v = make_float4(0.f, 0.f, 0.f, 0.f);
        if (row < n) {
            const float4* src = (row < nU) ? ((const float4*)Xu) + (size_t)row * 16
                                           : ((const float4*)Xv) + (size_t)(row - nU) * 16;
            v = src[c4];
        }
        *(float4*)(Xs + r * XS_STRIDE + c4 * 4) = v;
    }
    __syncthreads();

    const int tx = tid & 15;
    const int ty = tid >> 4;
    float4 acc[4];
    #pragma unroll
    for (int r = 0; r < 4; r++) acc[r] = make_float4(0.f, 0.f, 0.f, 0.f);

    #pragma unroll 8
    for (int k = 0; k < 64; k++) {
        float a0 = Xs[(ty * 4 + 0) * XS_STRIDE + k];
        float a1 = Xs[(ty * 4 + 1) * XS_STRIDE + k];
        float a2 = Xs[(ty * 4 + 2) * XS_STRIDE + k];
        float a3 = Xs[(ty * 4 + 3) * XS_STRIDE + k];
        float4 b = ((const float4*)(Rs + k * 64))[tx];
        acc[0].x += a0*b.x; acc[0].y += a0*b.y; acc[0].z += a0*b.z; acc[0].w += a0*b.w;
        acc[1].x += a1*b.x; acc[1].y += a1*b.y; acc[1].z += a1*b.z; acc[1].w += a1*b.w;
        acc[2].x += a2*b.x; acc[2].y += a2*b.y; acc[2].z += a2*b.z; acc[2].w += a2*b.w;
        acc[3].x += a3*b.x; acc[3].y += a3*b.y; acc[3].z += a3*b.z; acc[3].w += a3*b.w;
    }

    float fn = 1.f / (float)n;
    float scale[4], shift[4];
    #pragma unroll
    for (int j = 0; j < 4; j++) {
        int cc = tx * 4 + j;
        float mean = stats[cc] * fn;
        float var  = stats[64 + cc] * fn - mean * mean;
        float sc = gamma[cc] * rsqrtf(var + 1e-3f);
        scale[j] = sc;
        shift[j] = beta[cc] - mean * sc;
    }

    #pragma unroll
    for (int r = 0; r < 4; r++) {
        int row = rowBase + ty * 4 + r;
        if (row < n) {
            float4 yv = ((const float4*)(y2 + (size_t)row * 64))[tx];
            float o0 = acc[r].x + yv.x * scale[0] + shift[0];
            float o1 = acc[r].y + yv.y * scale[1] + shift[1];
            float o2 = acc[r].z + yv.z * scale[2] + shift[2];
            float o3 = acc[r].w + yv.w * scale[3] + shift[3];
            float4 ov;
            ov.x = o0 > 0.f ? o0 : 0.f;
            ov.y = o1 > 0.f ? o1 : 0.f;
            ov.z = o2 > 0.f ? o2 : 0.f;
            ov.w = o3 > 0.f ? o3 : 0.f;
            ((float4*)(out + (size_t)row * 64))[tx] = ov;
        }
    }
}

// ================= host =================
extern "C" void kernel_launch(void* const* d_in, const int* in_sizes, int n_in,
                              void* d_out, int out_size)
{
    const float* u   = (const float*)d_in[0];
    const float* v   = (const float*)d_in[1];
    const int*   es  = (const int*)  d_in[2];
    const int*   ee  = (const int*)  d_in[3];
    const float* Ui1 = (const float*)d_in[4];
    const float* Uj1 = (const float*)d_in[5];
    const float* Vi1 = (const float*)d_in[6];
    const float* Vj1 = (const float*)d_in[7];
    const float* bu1 = (const float*)d_in[8];
    const float* bv1 = (const float*)d_in[9];
    const float* Ui2 = (const float*)d_in[10];
    const float* Uj2 = (const float*)d_in[11];
    const float* Vi2 = (const float*)d_in[12];
    const float* Vj2 = (const float*)d_in[13];
    const float* bu2 = (const float*)d_in[14];
    const float* bv2 = (const float*)d_in[15];
    const float* R   = (const float*)d_in[16];
    const float* gamma1 = (const float*)d_in[17];
    const float* beta1  = (const float*)d_in[18];
    const float* gamma2 = (const float*)d_in[19];
    const float* beta2  = (const float*)d_in[20];

    const int nU = in_sizes[0] / 64;
    const int nV = in_sizes[1] / 64;
    const int n  = nU + nV;
    const int nE = in_sizes[2];

    float *pxvi, *py, *py2, *pst1, *pst2;
    unsigned *psuh;
    int *pcnt;
    cudaGetSymbolAddress((void**)&psuh, g_suh);
    cudaGetSymbolAddress((void**)&pxvi, g_xvi);
    cudaGetSymbolAddress((void**)&py,   g_y);
    cudaGetSymbolAddress((void**)&py2,  g_y2);
    cudaGetSymbolAddress((void**)&pst1, g_stats1);
    cudaGetSymbolAddress((void**)&pst2, g_stats2);
    cudaGetSymbolAddress((void**)&pcnt, g_cnt);

    cudaFuncSetAttribute(gemm4_kernel<false>, cudaFuncAttributeMaxDynamicSharedMemorySize, GEMM4_SMEM);
    cudaFuncSetAttribute(gemm4_kernel<true>,  cudaFuncAttributeMaxDynamicSharedMemorySize, GEMM4_SMEM);

    cudaMemsetAsync(pcnt, 0, (MAXN + 1) * sizeof(int));

    const int eb = (nE + 255) / 256;
    const int nb = (n + 255) / 256;
    const int gemmBlocks  = (n + 127) / 128;
    const int finalBlocks = (n + 63) / 64;
    const int aggBlocks   = (n + 31) / 32;

    hist_kernel<<<eb, 256>>>(ee, nE);
    scan_block_kernel<<<nb, 256>>>(n);
    scan_add_kernel<<<nb, 256>>>(n);

    // ---- stage 1 GEMM (profiled slot #4) ----
    gemm4_kernel<false><<<gemmBlocks, 256, GEMM4_SMEM>>>(u, v, nU,
                                                         Ui1, Uj1, Vi1, Vj1, bu1, bv1,
                                                         nullptr, nullptr, nullptr,
                                                         psuh, py, pxvi, n);
    scatter_kernel<<<eb, 256>>>(es, ee, nE);
    agg_kernel<<<aggBlocks, 256>>>(pxvi, psuh, py, pst1, n);

    // ---- stage 2 (BN1+ReLU fused into X load) ----
    gemm4_kernel<true><<<gemmBlocks, 256, GEMM4_SMEM>>>(py, py, n,
                                                        Ui2, Uj2, Vi2, Vj2, bu2, bv2,
                                                        pst1, gamma1, beta1,
                                                        psuh, py2, pxvi, n);
    agg_kernel<<<aggBlocks, 256>>>(pxvi, psuh, py2, pst2, n);

    // ---- final: relu(BN2(y2) + x_in @ R) ----
    final_kernel<<<finalBlocks, 256>>>(u, v, nU, R, py2, pst2, gamma2, beta2, (float*)d_out, n);
}

// round 11
// speedup vs baseline: 3.0421x; 1.3504x over previous
#include <cuda_runtime.h>
#include <cuda_fp16.h>
#include <math.h>

#define D 64
#define MAXN 100000
#define MAXE 1100000

// ---------------- static device scratch ----------------
// packed per-node record: 64 x half2(ui[c], vj[c]+bv[c])  = 256 B
__device__ unsigned g_suh[MAXN * 64];
__device__ float g_xvi[MAXN * D];
__device__ float g_y  [MAXN * D];    // stage1 output
__device__ float g_y2 [MAXN * D];    // stage2 output
__device__ float g_stats1[2 * D];
__device__ float g_stats2[2 * D];
// CSR (edges sorted by destination)
__device__ int g_cnt[MAXN + 1];
__device__ int g_off[MAXN + 1];
__device__ int g_cur[MAXN];
__device__ int g_srcSorted[MAXE];
__device__ int g_bsum[512];

// ================= CSR build =================
__global__ void hist_kernel(const int* __restrict__ ee, int nE)
{
    int e = blockIdx.x * blockDim.x + threadIdx.x;
    if (e < nE) atomicAdd(&g_cnt[ee[e]], 1);
}

__global__ void scan_block_kernel(int n)
{
    __shared__ int sh[256];
    int tid = threadIdx.x;
    int i = blockIdx.x * 256 + tid;
    int v = (i < n) ? g_cnt[i] : 0;
    sh[tid] = v;
    __syncthreads();
    #pragma unroll
    for (int ofs = 1; ofs < 256; ofs <<= 1) {
        int x = (tid >= ofs) ? sh[tid - ofs] : 0;
        __syncthreads();
        sh[tid] += x;
        __syncthreads();
    }
    if (i < n) g_off[i] = sh[tid] - v;
    if (tid == 255) g_bsum[blockIdx.x] = sh[255];
}

__global__ void scan_add_kernel(int n)
{
    __shared__ int s_prefix;
    const int bid = blockIdx.x;
    if (bid == 0 && threadIdx.x < 128) {
        g_stats1[threadIdx.x] = 0.f;
        g_stats2[threadIdx.x] = 0.f;
    }
    if (threadIdx.x < 32) {
        int s = 0;
        for (int i = threadIdx.x; i < bid; i += 32) s += g_bsum[i];
        #pragma unroll
        for (int o = 16; o; o >>= 1) s += __shfl_down_sync(0xffffffffu, s, o);
        if (threadIdx.x == 0) s_prefix = s;
    }
    __syncthreads();
    int i = bid * 256 + threadIdx.x;
    if (i < n) {
        int o = g_off[i] + s_prefix;
        g_off[i] = o;
        g_cur[i] = o;
        if (i == n - 1) g_off[n] = o + g_cnt[i];
    }
}

__global__ void scatter_kernel(const int* __restrict__ es, const int* __restrict__ ee, int nE)
{
    int e = blockIdx.x * blockDim.x + threadIdx.x;
    if (e < nE) {
        int d = ee[e];
        int p = atomicAdd(&g_cur[d], 1);
        g_srcSorted[p] = es[e];
    }
}

// ================= tf32 mma helpers =================
__device__ __forceinline__ unsigned f2tf32(float x)
{
    unsigned r;
    asm("cvt.rna.tf32.f32 %0, %1;" : "=r"(r) : "f"(x));
    return r;
}

__device__ __forceinline__ void mma_tf32(float* d, unsigned a0, unsigned a1,
                                         unsigned a2, unsigned a3,
                                         unsigned b0, unsigned b1)
{
    asm volatile(
        "mma.sync.aligned.m16n8k8.row.col.f32.tf32.tf32.f32 "
        "{%0,%1,%2,%3}, {%4,%5,%6,%7}, {%8,%9}, {%0,%1,%2,%3};"
        : "+f"(d[0]), "+f"(d[1]), "+f"(d[2]), "+f"(d[3])
        : "r"(a0), "r"(a1), "r"(a2), "r"(a3), "r"(b0), "r"(b1));
}

__device__ __forceinline__ unsigned pack_h2(float a, float b)
{
    __half2 h = __floats2half2_rn(a, b);
    return *reinterpret_cast<unsigned*>(&h);
}

// ================= fused 4-matrix GEMM via tf32 tensor cores =================
// Block: 128 rows (two 64-row subtiles, acc reused) x 256 cols, K=64, 8 warps.
#define WS_STRIDE 264
#define AS_STRIDE 68
#define GEMM4_SMEM (64*WS_STRIDE*4 + 64*AS_STRIDE*4)

template<bool BN>
__global__ void __launch_bounds__(256, 2)
gemm4_kernel(const float* __restrict__ X, const float* __restrict__ Xv, int nU,
             const float* __restrict__ Ui, const float* __restrict__ Uj,
             const float* __restrict__ Vi, const float* __restrict__ Vj,
             const float* __restrict__ bu, const float* __restrict__ bv,
             const float* __restrict__ stats, const float* __restrict__ gamma,
             const float* __restrict__ beta,
             unsigned* __restrict__ suh, float* __restrict__ y,
             float* __restrict__ xvi,
             int n)
{
    extern __shared__ float smem[];
    unsigned* Ws = (unsigned*)smem;                       // [64][264] tf32 bits
    unsigned* As = (unsigned*)(smem + 64 * WS_STRIDE);    // [64][68]  tf32 bits
    __shared__ float s_scale[64], s_shift[64];
    const int tid = threadIdx.x;
    const int rowBase0 = blockIdx.x * 128;

    if (BN) {
        if (tid < 64) {
            float fn = 1.f / (float)n;
            float mean = stats[tid] * fn;
            float var  = stats[64 + tid] * fn - mean * mean;
            float sc = gamma[tid] * rsqrtf(var + 1e-3f);
            s_scale[tid] = sc;
            s_shift[tid] = beta[tid] - mean * sc;
        }
        __syncthreads();
    }

    {
        const float* mats[4] = {Ui, Uj, Vi, Vj};
        #pragma unroll
        for (int m = 0; m < 4; m++) {
            const float4* src = (const float4*)mats[m];
            for (int i = tid; i < 1024; i += 256) {
                int k = i >> 4, j4 = i & 15;
                float4 w = src[i];
                uint4 p;
                p.x = f2tf32(w.x); p.y = f2tf32(w.y);
                p.z = f2tf32(w.z); p.w = f2tf32(w.w);
                *(uint4*)(Ws + k * WS_STRIDE + m * 64 + j4 * 4) = p;
            }
        }
    }

    const int warp = tid >> 5;
    const int lane = tid & 31;
    const int g = lane >> 2;
    const int t = lane & 3;
    const int nbase = warp * 8;
    const int c = nbase + 2 * t;
    float2 bu2 = *(const float2*)(bu + c);
    float2 bv2 = *(const float2*)(bv + c);

    #pragma unroll 1
    for (int st = 0; st < 2; st++) {
        const int rowBase = rowBase0 + st * 64;
        if (rowBase >= n) break;

        for (int i = tid; i < 1024; i += 256) {
            int r = i >> 4, c4 = i & 15;
            int row = rowBase + r;
            float4 v = make_float4(0.f, 0.f, 0.f, 0.f);
            if (row < n) {
                const float4* src = (row < nU) ? ((const float4*)X) + (size_t)row * 16
                                               : ((const float4*)Xv) + (size_t)(row - nU) * 16;
                v = src[c4];
            }
            if (BN) {
                int cc = c4 * 4;
                v.x = fmaxf(v.x * s_scale[cc+0] + s_shift[cc+0], 0.f);
                v.y = fmaxf(v.y * s_scale[cc+1] + s_shift[cc+1], 0.f);
                v.z = fmaxf(v.z * s_scale[cc+2] + s_shift[cc+2], 0.f);
                v.w = fmaxf(v.w * s_scale[cc+3] + s_shift[cc+3], 0.f);
            }
            uint4 p;
            p.x = f2tf32(v.x); p.y = f2tf32(v.y);
            p.z = f2tf32(v.z); p.w = f2tf32(v.w);
            *(uint4*)(As + r * AS_STRIDE + c4 * 4) = p;
        }
        __syncthreads();

        float acc[4][4][4];   // [mtile][matrix][c0..c3]
        #pragma unroll
        for (int mt = 0; mt < 4; mt++)
            #pragma unroll
            for (int nt = 0; nt < 4; nt++)
                #pragma unroll
                for (int cc = 0; cc < 4; cc++) acc[mt][nt][cc] = 0.f;

        #pragma unroll
        for (int k0 = 0; k0 < 64; k0 += 8) {
            unsigned b[4][2];
            #pragma unroll
            for (int nt = 0; nt < 4; nt++) {
                int cb = nt * 64 + nbase;
                b[nt][0] = Ws[(k0 + t)     * WS_STRIDE + cb + g];
                b[nt][1] = Ws[(k0 + t + 4) * WS_STRIDE + cb + g];
            }
            #pragma unroll
            for (int mt = 0; mt < 4; mt++) {
                int r0 = mt * 16;
                unsigned a0 = As[(r0 + g)     * AS_STRIDE + k0 + t];
                unsigned a1 = As[(r0 + g + 8) * AS_STRIDE + k0 + t];
                unsigned a2 = As[(r0 + g)     * AS_STRIDE + k0 + t + 4];
                unsigned a3 = As[(r0 + g + 8) * AS_STRIDE + k0 + t + 4];
                #pragma unroll
                for (int nt = 0; nt < 4; nt++)
                    mma_tf32(acc[mt][nt], a0, a1, a2, a3, b[nt][0], b[nt][1]);
            }
        }

        #pragma unroll
        for (int mt = 0; mt < 4; mt++) {
            #pragma unroll
            for (int h = 0; h < 2; h++) {
                int row = rowBase + mt * 16 + g + 8 * h;
                if (row < n) {
                    float u0  = acc[mt][0][2*h],   u1  = acc[mt][0][2*h+1];
                    float j0  = acc[mt][1][2*h] + bu2.x, j1 = acc[mt][1][2*h+1] + bu2.y;
                    float vi0 = acc[mt][2][2*h],   vi1 = acc[mt][2][2*h+1];
                    float vj0 = acc[mt][3][2*h] + bv2.x, vj1 = acc[mt][3][2*h+1] + bv2.y;
                    *(float2*)(y   + (size_t)row * 64 + c) = make_float2(j0, j1);
                    *(float2*)(xvi + (size_t)row * 64 + c) = make_float2(vi0, vi1);
                    uint2 pk;
                    pk.x = pack_h2(u0, vj0);
                    pk.y = pack_h2(u1, vj1);
                    *(uint2*)(suh + (size_t)row * 64 + c) = pk;
                }
            }
        }
        __syncthreads();
    }
}

// ================= per-node aggregation: tanh-based sigmoid (1 MUFU, no div) =================
__device__ __forceinline__ float sigmul(float ui, float xh)
{
    // ui * sigmoid(2*xh) = ui * (0.5*tanh(xh) + 0.5)
    float th;
    asm("tanh.approx.f32 %0, %1;" : "=f"(th) : "f"(xh));
    return ui * fmaf(0.5f, th, 0.5f);
}

__device__ __forceinline__ void edge_acc(float4& acc, const float4& vih, uint4 pk)
{
    // vih = 0.5*vi (precomputed); xh = 0.5*(vi+vj) = vih + 0.5*vj
    float2 f0 = __half22float2(*reinterpret_cast<__half2*>(&pk.x));
    float2 f1 = __half22float2(*reinterpret_cast<__half2*>(&pk.y));
    float2 f2 = __half22float2(*reinterpret_cast<__half2*>(&pk.z));
    float2 f3 = __half22float2(*reinterpret_cast<__half2*>(&pk.w));
    acc.x += sigmul(f0.x, fmaf(0.5f, f0.y, vih.x));
    acc.y += sigmul(f1.x, fmaf(0.5f, f1.y, vih.y));
    acc.z += sigmul(f2.x, fmaf(0.5f, f2.y, vih.z));
    acc.w += sigmul(f3.x, fmaf(0.5f, f3.y, vih.w));
}

__global__ void agg_kernel(const float* __restrict__ xvi, const unsigned* __restrict__ suh,
                           float* __restrict__ y, float* __restrict__ stats, int n)
{
    __shared__ float s_sum[64], s_sum2[64];
    const int tid = threadIdx.x;
    if (tid < 64) { s_sum[tid] = 0.f; s_sum2[tid] = 0.f; }
    __syncthreads();

    const int warp = tid >> 5;
    const int lane = tid & 31;
    const int half = lane >> 4;
    const int l4   = lane & 15;
    const int nodeBase = blockIdx.x * 32 + warp * 4;

    float4 st1 = make_float4(0.f, 0.f, 0.f, 0.f);
    float4 st2 = make_float4(0.f, 0.f, 0.f, 0.f);

    #pragma unroll 1
    for (int q = 0; q < 4; q++) {
        const int node = nodeBase + q;
        if (node >= n) break;

        float4 vi = ((const float4*)(xvi + (size_t)node * 64))[l4];
        float4 vih = make_float4(0.5f * vi.x, 0.5f * vi.y, 0.5f * vi.z, 0.5f * vi.w);
        float4 acc = make_float4(0.f, 0.f, 0.f, 0.f);
        const int p0 = g_off[node];
        const int p1 = g_off[node + 1];

        int pp = p0 + half;
        for (; pp + 6 < p1; pp += 8) {
            int b0 = __ldg(g_srcSorted + pp);
            int b1 = __ldg(g_srcSorted + pp + 2);
            int b2 = __ldg(g_srcSorted + pp + 4);
            int b3 = __ldg(g_srcSorted + pp + 6);
            uint4 k0 = __ldg((const uint4*)(suh + (size_t)b0 * 64) + l4);
            uint4 k1 = __ldg((const uint4*)(suh + (size_t)b1 * 64) + l4);
            uint4 k2 = __ldg((const uint4*)(suh + (size_t)b2 * 64) + l4);
            uint4 k3 = __ldg((const uint4*)(suh + (size_t)b3 * 64) + l4);
            edge_acc(acc, vih, k0);
            edge_acc(acc, vih, k1);
            edge_acc(acc, vih, k2);
            edge_acc(acc, vih, k3);
        }
        for (; pp < p1; pp += 2) {
            int b = __ldg(g_srcSorted + pp);
            uint4 k = __ldg((const uint4*)(suh + (size_t)b * 64) + l4);
            edge_acc(acc, vih, k);
        }

        acc.x += __shfl_xor_sync(0xffffffffu, acc.x, 16);
        acc.y += __shfl_xor_sync(0xffffffffu, acc.y, 16);
        acc.z += __shfl_xor_sync(0xffffffffu, acc.z, 16);
        acc.w += __shfl_xor_sync(0xffffffffu, acc.w, 16);

        if (half == 0) {
            float4 base = ((const float4*)(y + (size_t)node * 64))[l4];
            acc.x += base.x; acc.y += base.y; acc.z += base.z; acc.w += base.w;
            ((float4*)(y + (size_t)node * 64))[l4] = acc;
            st1.x += acc.x; st1.y += acc.y; st1.z += acc.z; st1.w += acc.w;
            st2.x += acc.x * acc.x; st2.y += acc.y * acc.y;
            st2.z += acc.z * acc.z; st2.w += acc.w * acc.w;
        }
    }

    if (half == 0) {
        int cc = l4 * 4;
        atomicAdd(&s_sum[cc + 0], st1.x);  atomicAdd(&s_sum2[cc + 0], st2.x);
        atomicAdd(&s_sum[cc + 1], st1.y);  atomicAdd(&s_sum2[cc + 1], st2.y);
        atomicAdd(&s_sum[cc + 2], st1.z);  atomicAdd(&s_sum2[cc + 2], st2.z);
        atomicAdd(&s_sum[cc + 3], st1.w);  atomicAdd(&s_sum2[cc + 3], st2.w);
    }
    __syncthreads();
    if (tid < 64) {
        atomicAdd(stats + tid,      s_sum[tid]);
        atomicAdd(stats + 64 + tid, s_sum2[tid]);
    }
}

// ================= final: out = relu( BN2(y2) + x_in @ R ) via tf32 MMA =================
#define RS_STRIDE 72
#define FAS_STRIDE 68

__global__ void __launch_bounds__(256)
final_kernel(const float* __restrict__ Xu, const float* __restrict__ Xv, int nU,
             const float* __restrict__ R,
             const float* __restrict__ y2, const float* __restrict__ stats,
             const float* __restrict__ gamma, const float* __restrict__ beta,
             float* __restrict__ out, int n)
{
    __shared__ unsigned Rs[64 * RS_STRIDE];   // tf32 bits
    __shared__ unsigned As[64 * FAS_STRIDE];
    const int tid = threadIdx.x;
    const int rowBase = blockIdx.x * 64;

    // stage R as tf32
    for (int i = tid; i < 1024; i += 256) {
        int k = i >> 4, j4 = i & 15;
        float4 w = ((const float4*)R)[i];
        uint4 p;
        p.x = f2tf32(w.x); p.y = f2tf32(w.y);
        p.z = f2tf32(w.z); p.w = f2tf32(w.w);
        *(uint4*)(Rs + k * RS_STRIDE + j4 * 4) = p;
    }
    // stage X tile as tf32 (direct concat read)
    for (int i = tid; i < 1024; i += 256) {
        int r = i >> 4, c4 = i & 15;
        int row = rowBase + r;
        float4 v = make_float4(0.f, 0.f, 0.f, 0.f);
        if (row < n) {
            const float4* src = (row < nU) ? ((const float4*)Xu) + (size_t)row * 16
                                           : ((const float4*)Xv) + (size_t)(row - nU) * 16;
            v = src[c4];
        }
        uint4 p;
        p.x = f2tf32(v.x); p.y = f2tf32(v.y);
        p.z = f2tf32(v.z); p.w = f2tf32(v.w);
        *(uint4*)(As + r * FAS_STRIDE + c4 * 4) = p;
    }
    __syncthreads();

    const int warp = tid >> 5;
    const int lane = tid & 31;
    const int g = lane >> 2;
    const int t = lane & 3;
    const int cb = warp * 8;

    float acc[4][4];
    #pragma unroll
    for (int mt = 0; mt < 4; mt++)
        #pragma unroll
        for (int cc = 0; cc < 4; cc++) acc[mt][cc] = 0.f;

    #pragma unroll
    for (int k0 = 0; k0 < 64; k0 += 8) {
        unsigned b0 = Rs[(k0 + t)     * RS_STRIDE + cb + g];
        unsigned b1 = Rs[(k0 + t + 4) * RS_STRIDE + cb + g];
        #pragma unroll
        for (int mt = 0; mt < 4; mt++) {
            int r0 = mt * 16;
            unsigned a0 = As[(r0 + g)     * FAS_STRIDE + k0 + t];
            unsigned a1 = As[(r0 + g + 8) * FAS_STRIDE + k0 + t];
            unsigned a2 = As[(r0 + g)     * FAS_STRIDE + k0 + t + 4];
            unsigned a3 = As[(r0 + g + 8) * FAS_STRIDE + k0 + t + 4];
            mma_tf32(acc[mt], a0, a1, a2, a3, b0, b1);
        }
    }

    // per-column BN coefficients for cols c, c+1
    const int c = cb + 2 * t;
    float fn = 1.f / (float)n;
    float scale[2], shift[2];
    #pragma unroll
    for (int j = 0; j < 2; j++) {
        int cc = c + j;
        float mean = stats[cc] * fn;
        float var  = stats[64 + cc] * fn - mean * mean;
        float sc = gamma[cc] * rsqrtf(var + 1e-3f);
        scale[j] = sc;
        shift[j] = beta[cc] - mean * sc;
    }

    #pragma unroll
    for (int mt = 0; mt < 4; mt++) {
        #pragma unroll
        for (int h = 0; h < 2; h++) {
            int row = rowBase + mt * 16 + g + 8 * h;
            if (row < n) {
                float2 yv = *(const float2*)(y2 + (size_t)row * 64 + c);
                float o0 = acc[mt][2*h]   + yv.x * scale[0] + shift[0];
                float o1 = acc[mt][2*h+1] + yv.y * scale[1] + shift[1];
                float2 ov;
                ov.x = o0 > 0.f ? o0 : 0.f;
                ov.y = o1 > 0.f ? o1 : 0.f;
                *(float2*)(out + (size_t)row * 64 + c) = ov;
            }
        }
    }
}

// ================= host =================
extern "C" void kernel_launch(void* const* d_in, const int* in_sizes, int n_in,
                              void* d_out, int out_size)
{
    const float* u   = (const float*)d_in[0];
    const float* v   = (const float*)d_in[1];
    const int*   es  = (const int*)  d_in[2];
    const int*   ee  = (const int*)  d_in[3];
    const float* Ui1 = (const float*)d_in[4];
    const float* Uj1 = (const float*)d_in[5];
    const float* Vi1 = (const float*)d_in[6];
    const float* Vj1 = (const float*)d_in[7];
    const float* bu1 = (const float*)d_in[8];
    const float* bv1 = (const float*)d_in[9];
    const float* Ui2 = (const float*)d_in[10];
    const float* Uj2 = (const float*)d_in[11];
    const float* Vi2 = (const float*)d_in[12];
    const float* Vj2 = (const float*)d_in[13];
    const float* bu2 = (const float*)d_in[14];
    const float* bv2 = (const float*)d_in[15];
    const float* R   = (const float*)d_in[16];
    const float* gamma1 = (const float*)d_in[17];
    const float* beta1  = (const float*)d_in[18];
    const float* gamma2 = (const float*)d_in[19];
    const float* beta2  = (const float*)d_in[20];

    const int nU = in_sizes[0] / 64;
    const int nV = in_sizes[1] / 64;
    const int n  = nU + nV;
    const int nE = in_sizes[2];

    float *pxvi, *py, *py2, *pst1, *pst2;
    unsigned *psuh;
    int *pcnt;
    cudaGetSymbolAddress((void**)&psuh, g_suh);
    cudaGetSymbolAddress((void**)&pxvi, g_xvi);
    cudaGetSymbolAddress((void**)&py,   g_y);
    cudaGetSymbolAddress((void**)&py2,  g_y2);
    cudaGetSymbolAddress((void**)&pst1, g_stats1);
    cudaGetSymbolAddress((void**)&pst2, g_stats2);
    cudaGetSymbolAddress((void**)&pcnt, g_cnt);

    cudaFuncSetAttribute(gemm4_kernel<false>, cudaFuncAttributeMaxDynamicSharedMemorySize, GEMM4_SMEM);
    cudaFuncSetAttribute(gemm4_kernel<true>,  cudaFuncAttributeMaxDynamicSharedMemorySize, GEMM4_SMEM);

    cudaMemsetAsync(pcnt, 0, (MAXN + 1) * sizeof(int));

    const int eb = (nE + 255) / 256;
    const int nb = (n + 255) / 256;
    const int gemmBlocks  = (n + 127) / 128;
    const int finalBlocks = (n + 63) / 64;
    const int aggBlocks   = (n + 31) / 32;

    hist_kernel<<<eb, 256>>>(ee, nE);
    scan_block_kernel<<<nb, 256>>>(n);
    scan_add_kernel<<<nb, 256>>>(n);

    // ---- stage 1 GEMM (profiled slot #4) ----
    gemm4_kernel<false><<<gemmBlocks, 256, GEMM4_SMEM>>>(u, v, nU,
                                                         Ui1, Uj1, Vi1, Vj1, bu1, bv1,
                                                         nullptr, nullptr, nullptr,
                                                         psuh, py, pxvi, n);
    scatter_kernel<<<eb, 256>>>(es, ee, nE);
    agg_kernel<<<aggBlocks, 256>>>(pxvi, psuh, py, pst1, n);

    // ---- stage 2 (BN1+ReLU fused into X load) ----
    gemm4_kernel<true><<<gemmBlocks, 256, GEMM4_SMEM>>>(py, py, n,
                                                        Ui2, Uj2, Vi2, Vj2, bu2, bv2,
                                                        pst1, gamma1, beta1,
                                                        psuh, py2, pxvi, n);
    agg_kernel<<<aggBlocks, 256>>>(pxvi, psuh, py2, pst2, n);

    // ---- final: relu(BN2(y2) + x_in @ R) ----
    final_kernel<<<finalBlocks, 256>>>(u, v, nU, R, py2, pst2, gamma2, beta2, (float*)d_out, n);
}

// round 12
// speedup vs baseline: 3.1465x; 1.0343x over previous
#include <cuda_runtime.h>
#include <cuda_fp16.h>
#include <math.h>

#define D 64
#define MAXN 100000
#define MAXE 1100000

// ---------------- static device scratch ----------------
// packed per-node record: 64 x half2(ui[c], vj[c]+bv[c])  = 256 B
__device__ unsigned g_suh[MAXN * 64];
__device__ float g_xvi[MAXN * D];
__device__ float g_y  [MAXN * D];    // stage1 output
__device__ float g_y2 [MAXN * D];    // stage2 output
__device__ float g_stats1[2 * D];
__device__ float g_stats2[2 * D];
// CSR (edges sorted by destination)
__device__ int g_cnt[MAXN + 1];
__device__ int g_off[MAXN + 1];
__device__ int g_cur[MAXN];
__device__ int g_srcSorted[MAXE];
__device__ int g_bsum[512];

// ================= CSR build =================
__global__ void hist_kernel(const int* __restrict__ ee, int nE)
{
    int e = blockIdx.x * blockDim.x + threadIdx.x;
    if (e < nE) atomicAdd(&g_cnt[ee[e]], 1);
}

__global__ void scan_block_kernel(int n)
{
    __shared__ int sh[256];
    int tid = threadIdx.x;
    int i = blockIdx.x * 256 + tid;
    int v = (i < n) ? g_cnt[i] : 0;
    sh[tid] = v;
    __syncthreads();
    #pragma unroll
    for (int ofs = 1; ofs < 256; ofs <<= 1) {
        int x = (tid >= ofs) ? sh[tid - ofs] : 0;
        __syncthreads();
        sh[tid] += x;
        __syncthreads();
    }
    if (i < n) g_off[i] = sh[tid] - v;
    if (tid == 255) g_bsum[blockIdx.x] = sh[255];
}

__global__ void scan_add_kernel(int n)
{
    __shared__ int s_prefix;
    const int bid = blockIdx.x;
    if (bid == 0 && threadIdx.x < 128) {
        g_stats1[threadIdx.x] = 0.f;
        g_stats2[threadIdx.x] = 0.f;
    }
    if (threadIdx.x < 32) {
        int s = 0;
        for (int i = threadIdx.x; i < bid; i += 32) s += g_bsum[i];
        #pragma unroll
        for (int o = 16; o; o >>= 1) s += __shfl_down_sync(0xffffffffu, s, o);
        if (threadIdx.x == 0) s_prefix = s;
    }
    __syncthreads();
    int i = bid * 256 + threadIdx.x;
    if (i < n) {
        int o = g_off[i] + s_prefix;
        g_off[i] = o;
        g_cur[i] = o;
        if (i == n - 1) g_off[n] = o + g_cnt[i];
    }
}

__global__ void scatter_kernel(const int* __restrict__ es, const int* __restrict__ ee, int nE)
{
    int e = blockIdx.x * blockDim.x + threadIdx.x;
    if (e < nE) {
        int d = ee[e];
        int p = atomicAdd(&g_cur[d], 1);
        g_srcSorted[p] = es[e];
    }
}

// ================= tf32 mma helpers =================
__device__ __forceinline__ unsigned f2tf32(float x)
{
    unsigned r;
    asm("cvt.rna.tf32.f32 %0, %1;" : "=r"(r) : "f"(x));
    return r;
}

__device__ __forceinline__ void mma_tf32(float* d, unsigned a0, unsigned a1,
                                         unsigned a2, unsigned a3,
                                         unsigned b0, unsigned b1)
{
    asm volatile(
        "mma.sync.aligned.m16n8k8.row.col.f32.tf32.tf32.f32 "
        "{%0,%1,%2,%3}, {%4,%5,%6,%7}, {%8,%9}, {%0,%1,%2,%3};"
        : "+f"(d[0]), "+f"(d[1]), "+f"(d[2]), "+f"(d[3])
        : "r"(a0), "r"(a1), "r"(a2), "r"(a3), "r"(b0), "r"(b1));
}

__device__ __forceinline__ unsigned pack_h2(float a, float b)
{
    __half2 h = __floats2half2_rn(a, b);
    return *reinterpret_cast<unsigned*>(&h);
}

// ================= fused 4-matrix GEMM via tf32 tensor cores (persistent) =================
// Persistent blocks: W staged ONCE per block, then loop over 128-row tiles.
#define WS_STRIDE 264
#define AS_STRIDE 68
#define GEMM4_SMEM (64*WS_STRIDE*4 + 64*AS_STRIDE*4)

template<bool BN>
__global__ void __launch_bounds__(256, 2)
gemm4_kernel(const float* __restrict__ X, const float* __restrict__ Xv, int nU,
             const float* __restrict__ Ui, const float* __restrict__ Uj,
             const float* __restrict__ Vi, const float* __restrict__ Vj,
             const float* __restrict__ bu, const float* __restrict__ bv,
             const float* __restrict__ stats, const float* __restrict__ gamma,
             const float* __restrict__ beta,
             unsigned* __restrict__ suh, float* __restrict__ y,
             float* __restrict__ xvi,
             int n)
{
    extern __shared__ float smem[];
    unsigned* Ws = (unsigned*)smem;                       // [64][264] tf32 bits
    unsigned* As = (unsigned*)(smem + 64 * WS_STRIDE);    // [64][68]  tf32 bits
    __shared__ float s_scale[64], s_shift[64];
    const int tid = threadIdx.x;

    if (BN) {
        if (tid < 64) {
            float fn = 1.f / (float)n;
            float mean = stats[tid] * fn;
            float var  = stats[64 + tid] * fn - mean * mean;
            float sc = gamma[tid] * rsqrtf(var + 1e-3f);
            s_scale[tid] = sc;
            s_shift[tid] = beta[tid] - mean * sc;
        }
        __syncthreads();
    }

    // stage W once per (persistent) block
    {
        const float* mats[4] = {Ui, Uj, Vi, Vj};
        #pragma unroll
        for (int m = 0; m < 4; m++) {
            const float4* src = (const float4*)mats[m];
            for (int i = tid; i < 1024; i += 256) {
                int k = i >> 4, j4 = i & 15;
                float4 w = src[i];
                uint4 p;
                p.x = f2tf32(w.x); p.y = f2tf32(w.y);
                p.z = f2tf32(w.z); p.w = f2tf32(w.w);
                *(uint4*)(Ws + k * WS_STRIDE + m * 64 + j4 * 4) = p;
            }
        }
    }

    const int warp = tid >> 5;
    const int lane = tid & 31;
    const int g = lane >> 2;
    const int t = lane & 3;
    const int nbase = warp * 8;
    const int c = nbase + 2 * t;
    float2 bu2 = *(const float2*)(bu + c);
    float2 bv2 = *(const float2*)(bv + c);

    const int nTiles = (n + 127) / 128;

    for (int tile = blockIdx.x; tile < nTiles; tile += gridDim.x) {
        const int rowBase0 = tile * 128;

        #pragma unroll 1
        for (int st = 0; st < 2; st++) {
            const int rowBase = rowBase0 + st * 64;
            if (rowBase >= n) break;

            __syncthreads();   // protect As from previous subtile's readers
            for (int i = tid; i < 1024; i += 256) {
                int r = i >> 4, c4 = i & 15;
                int row = rowBase + r;
                float4 v = make_float4(0.f, 0.f, 0.f, 0.f);
                if (row < n) {
                    const float4* src = (row < nU) ? ((const float4*)X) + (size_t)row * 16
                                                   : ((const float4*)Xv) + (size_t)(row - nU) * 16;
                    v = src[c4];
                }
                if (BN) {
                    int cc = c4 * 4;
                    v.x = fmaxf(v.x * s_scale[cc+0] + s_shift[cc+0], 0.f);
                    v.y = fmaxf(v.y * s_scale[cc+1] + s_shift[cc+1], 0.f);
                    v.z = fmaxf(v.z * s_scale[cc+2] + s_shift[cc+2], 0.f);
                    v.w = fmaxf(v.w * s_scale[cc+3] + s_shift[cc+3], 0.f);
                }
                uint4 p;
                p.x = f2tf32(v.x); p.y = f2tf32(v.y);
                p.z = f2tf32(v.z); p.w = f2tf32(v.w);
                *(uint4*)(As + r * AS_STRIDE + c4 * 4) = p;
            }
            __syncthreads();

            float acc[4][4][4];   // [mtile][matrix][c0..c3]
            #pragma unroll
            for (int mt = 0; mt < 4; mt++)
                #pragma unroll
                for (int nt = 0; nt < 4; nt++)
                    #pragma unroll
                    for (int cc = 0; cc < 4; cc++) acc[mt][nt][cc] = 0.f;

            #pragma unroll
            for (int k0 = 0; k0 < 64; k0 += 8) {
                unsigned b[4][2];
                #pragma unroll
                for (int nt = 0; nt < 4; nt++) {
                    int cb = nt * 64 + nbase;
                    b[nt][0] = Ws[(k0 + t)     * WS_STRIDE + cb + g];
                    b[nt][1] = Ws[(k0 + t + 4) * WS_STRIDE + cb + g];
                }
                #pragma unroll
                for (int mt = 0; mt < 4; mt++) {
                    int r0 = mt * 16;
                    unsigned a0 = As[(r0 + g)     * AS_STRIDE + k0 + t];
                    unsigned a1 = As[(r0 + g + 8) * AS_STRIDE + k0 + t];
                    unsigned a2 = As[(r0 + g)     * AS_STRIDE + k0 + t + 4];
                    unsigned a3 = As[(r0 + g + 8) * AS_STRIDE + k0 + t + 4];
                    #pragma unroll
                    for (int nt = 0; nt < 4; nt++)
                        mma_tf32(acc[mt][nt], a0, a1, a2, a3, b[nt][0], b[nt][1]);
                }
            }

            #pragma unroll
            for (int mt = 0; mt < 4; mt++) {
                #pragma unroll
                for (int h = 0; h < 2; h++) {
                    int row = rowBase + mt * 16 + g + 8 * h;
                    if (row < n) {
                        float u0  = acc[mt][0][2*h],   u1  = acc[mt][0][2*h+1];
                        float j0  = acc[mt][1][2*h] + bu2.x, j1 = acc[mt][1][2*h+1] + bu2.y;
                        float vi0 = acc[mt][2][2*h],   vi1 = acc[mt][2][2*h+1];
                        float vj0 = acc[mt][3][2*h] + bv2.x, vj1 = acc[mt][3][2*h+1] + bv2.y;
                        *(float2*)(y   + (size_t)row * 64 + c) = make_float2(j0, j1);
                        *(float2*)(xvi + (size_t)row * 64 + c) = make_float2(vi0, vi1);
                        uint2 pk;
                        pk.x = pack_h2(u0, vj0);
                        pk.y = pack_h2(u1, vj1);
                        *(uint2*)(suh + (size_t)row * 64 + c) = pk;
                    }
                }
            }
        }
    }
}

// ================= per-node aggregation: tanh-based sigmoid =================
__device__ __forceinline__ float sigmul(float ui, float xh)
{
    float th;
    asm("tanh.approx.f32 %0, %1;" : "=f"(th) : "f"(xh));
    return ui * fmaf(0.5f, th, 0.5f);
}

__device__ __forceinline__ void edge_acc(float4& acc, const float4& vih, uint4 pk)
{
    float2 f0 = __half22float2(*reinterpret_cast<__half2*>(&pk.x));
    float2 f1 = __half22float2(*reinterpret_cast<__half2*>(&pk.y));
    float2 f2 = __half22float2(*reinterpret_cast<__half2*>(&pk.z));
    float2 f3 = __half22float2(*reinterpret_cast<__half2*>(&pk.w));
    acc.x += sigmul(f0.x, fmaf(0.5f, f0.y, vih.x));
    acc.y += sigmul(f1.x, fmaf(0.5f, f1.y, vih.y));
    acc.z += sigmul(f2.x, fmaf(0.5f, f2.y, vih.z));
    acc.w += sigmul(f3.x, fmaf(0.5f, f3.y, vih.w));
}

__global__ void agg_kernel(const float* __restrict__ xvi, const unsigned* __restrict__ suh,
                           float* __restrict__ y, float* __restrict__ stats, int n)
{
    __shared__ float s_sum[64], s_sum2[64];
    const int tid = threadIdx.x;
    if (tid < 64) { s_sum[tid] = 0.f; s_sum2[tid] = 0.f; }
    __syncthreads();

    const int warp = tid >> 5;
    const int lane = tid & 31;
    const int half = lane >> 4;
    const int l4   = lane & 15;
    const int nodeBase = blockIdx.x * 32 + warp * 4;

    float4 st1 = make_float4(0.f, 0.f, 0.f, 0.f);
    float4 st2 = make_float4(0.f, 0.f, 0.f, 0.f);

    #pragma unroll 1
    for (int q = 0; q < 4; q++) {
        const int node = nodeBase + q;
        if (node >= n) break;

        float4 vi = ((const float4*)(xvi + (size_t)node * 64))[l4];
        float4 base = ((const float4*)(y + (size_t)node * 64))[l4];  // prefetch x@Uj+bu
        float4 vih = make_float4(0.5f * vi.x, 0.5f * vi.y, 0.5f * vi.z, 0.5f * vi.w);
        float4 acc = make_float4(0.f, 0.f, 0.f, 0.f);
        const int p0 = g_off[node];
        const int p1 = g_off[node + 1];

        int pp = p0 + half;
        // 8-edge tier (4 per half in flight)
        for (; pp + 6 < p1; pp += 8) {
            int b0 = __ldg(g_srcSorted + pp);
            int b1 = __ldg(g_srcSorted + pp + 2);
            int b2 = __ldg(g_srcSorted + pp + 4);
            int b3 = __ldg(g_srcSorted + pp + 6);
            uint4 k0 = __ldg((const uint4*)(suh + (size_t)b0 * 64) + l4);
            uint4 k1 = __ldg((const uint4*)(suh + (size_t)b1 * 64) + l4);
            uint4 k2 = __ldg((const uint4*)(suh + (size_t)b2 * 64) + l4);
            uint4 k3 = __ldg((const uint4*)(suh + (size_t)b3 * 64) + l4);
            edge_acc(acc, vih, k0);
            edge_acc(acc, vih, k1);
            edge_acc(acc, vih, k2);
            edge_acc(acc, vih, k3);
        }
        // 4-edge tier (2 per half in flight)
        for (; pp + 2 < p1; pp += 4) {
            int b0 = __ldg(g_srcSorted + pp);
            int b1 = __ldg(g_srcSorted + pp + 2);
            uint4 k0 = __ldg((const uint4*)(suh + (size_t)b0 * 64) + l4);
            uint4 k1 = __ldg((const uint4*)(suh + (size_t)b1 * 64) + l4);
            edge_acc(acc, vih, k0);
            edge_acc(acc, vih, k1);
        }
        // tail
        for (; pp < p1; pp += 2) {
            int b = __ldg(g_srcSorted + pp);
            uint4 k = __ldg((const uint4*)(suh + (size_t)b * 64) + l4);
            edge_acc(acc, vih, k);
        }

        acc.x += __shfl_xor_sync(0xffffffffu, acc.x, 16);
        acc.y += __shfl_xor_sync(0xffffffffu, acc.y, 16);
        acc.z += __shfl_xor_sync(0xffffffffu, acc.z, 16);
        acc.w += __shfl_xor_sync(0xffffffffu, acc.w, 16);

        if (half == 0) {
            acc.x += base.x; acc.y += base.y; acc.z += base.z; acc.w += base.w;
            ((float4*)(y + (size_t)node * 64))[l4] = acc;
            st1.x += acc.x; st1.y += acc.y; st1.z += acc.z; st1.w += acc.w;
            st2.x += acc.x * acc.x; st2.y += acc.y * acc.y;
            st2.z += acc.z * acc.z; st2.w += acc.w * acc.w;
        }
    }

    if (half == 0) {
        int cc = l4 * 4;
        atomicAdd(&s_sum[cc + 0], st1.x);  atomicAdd(&s_sum2[cc + 0], st2.x);
        atomicAdd(&s_sum[cc + 1], st1.y);  atomicAdd(&s_sum2[cc + 1], st2.y);
        atomicAdd(&s_sum[cc + 2], st1.z);  atomicAdd(&s_sum2[cc + 2], st2.z);
        atomicAdd(&s_sum[cc + 3], st1.w);  atomicAdd(&s_sum2[cc + 3], st2.w);
    }
    __syncthreads();
    if (tid < 64) {
        atomicAdd(stats + tid,      s_sum[tid]);
        atomicAdd(stats + 64 + tid, s_sum2[tid]);
    }
}

// ================= final: out = relu( BN2(y2) + x_in @ R ) via tf32 MMA =================
#define RS_STRIDE 72
#define FAS_STRIDE 68

__global__ void __launch_bounds__(256)
final_kernel(const float* __restrict__ Xu, const float* __restrict__ Xv, int nU,
             const float* __restrict__ R,
             const float* __restrict__ y2, const float* __restrict__ stats,
             const float* __restrict__ gamma, const float* __restrict__ beta,
             float* __restrict__ out, int n)
{
    __shared__ unsigned Rs[64 * RS_STRIDE];
    __shared__ unsigned As[64 * FAS_STRIDE];
    const int tid = threadIdx.x;
    const int rowBase = blockIdx.x * 64;

    for (int i = tid; i < 1024; i += 256) {
        int k = i >> 4, j4 = i & 15;
        float4 w = ((const float4*)R)[i];
        uint4 p;
        p.x = f2tf32(w.x); p.y = f2tf32(w.y);
        p.z = f2tf32(w.z); p.w = f2tf32(w.w);
        *(uint4*)(Rs + k * RS_STRIDE + j4 * 4) = p;
    }
    for (int i = tid; i < 1024; i += 256) {
        int r = i >> 4, c4 = i & 15;
        int row = rowBase + r;
        float4 v = make_float4(0.f, 0.f, 0.f, 0.f);
        if (row < n) {
            const float4* src = (row < nU) ? ((const float4*)Xu) + (size_t)row * 16
                                           : ((const float4*)Xv) + (size_t)(row - nU) * 16;
            v = src[c4];
        }
        uint4 p;
        p.x = f2tf32(v.x); p.y = f2tf32(v.y);
        p.z = f2tf32(v.z); p.w = f2tf32(v.w);
        *(uint4*)(As + r * FAS_STRIDE + c4 * 4) = p;
    }
    __syncthreads();

    const int warp = tid >> 5;
    const int lane = tid & 31;
    const int g = lane >> 2;
    const int t = lane & 3;
    const int cb = warp * 8;

    float acc[4][4];
    #pragma unroll
    for (int mt = 0; mt < 4; mt++)
        #pragma unroll
        for (int cc = 0; cc < 4; cc++) acc[mt][cc] = 0.f;

    #pragma unroll
    for (int k0 = 0; k0 < 64; k0 += 8) {
        unsigned b0 = Rs[(k0 + t)     * RS_STRIDE + cb + g];
        unsigned b1 = Rs[(k0 + t + 4) * RS_STRIDE + cb + g];
        #pragma unroll
        for (int mt = 0; mt < 4; mt++) {
            int r0 = mt * 16;
            unsigned a0 = As[(r0 + g)     * FAS_STRIDE + k0 + t];
            unsigned a1 = As[(r0 + g + 8) * FAS_STRIDE + k0 + t];
            unsigned a2 = As[(r0 + g)     * FAS_STRIDE + k0 + t + 4];
            unsigned a3 = As[(r0 + g + 8) * FAS_STRIDE + k0 + t + 4];
            mma_tf32(acc[mt], a0, a1, a2, a3, b0, b1);
        }
    }

    const int c = cb + 2 * t;
    float fn = 1.f / (float)n;
    float scale[2], shift[2];
    #pragma unroll
    for (int j = 0; j < 2; j++) {
        int cc = c + j;
        float mean = stats[cc] * fn;
        float var  = stats[64 + cc] * fn - mean * mean;
        float sc = gamma[cc] * rsqrtf(var + 1e-3f);
        scale[j] = sc;
        shift[j] = beta[cc] - mean * sc;
    }

    #pragma unroll
    for (int mt = 0; mt < 4; mt++) {
        #pragma unroll
        for (int h = 0; h < 2; h++) {
            int row = rowBase + mt * 16 + g + 8 * h;
            if (row < n) {
                float2 yv = *(const float2*)(y2 + (size_t)row * 64 + c);
                float o0 = acc[mt][2*h]   + yv.x * scale[0] + shift[0];
                float o1 = acc[mt][2*h+1] + yv.y * scale[1] + shift[1];
                float2 ov;
                ov.x = o0 > 0.f ? o0 : 0.f;
                ov.y = o1 > 0.f ? o1 : 0.f;
                *(float2*)(out + (size_t)row * 64 + c) = ov;
            }
        }
    }
}

// ================= host =================
extern "C" void kernel_launch(void* const* d_in, const int* in_sizes, int n_in,
                              void* d_out, int out_size)
{
    const float* u   = (const float*)d_in[0];
    const float* v   = (const float*)d_in[1];
    const int*   es  = (const int*)  d_in[2];
    const int*   ee  = (const int*)  d_in[3];
    const float* Ui1 = (const float*)d_in[4];
    const float* Uj1 = (const float*)d_in[5];
    const float* Vi1 = (const float*)d_in[6];
    const float* Vj1 = (const float*)d_in[7];
    const float* bu1 = (const float*)d_in[8];
    const float* bv1 = (const float*)d_in[9];
    const float* Ui2 = (const float*)d_in[10];
    const float* Uj2 = (const float*)d_in[11];
    const float* Vi2 = (const float*)d_in[12];
    const float* Vj2 = (const float*)d_in[13];
    const float* bu2 = (const float*)d_in[14];
    const float* bv2 = (const float*)d_in[15];
    const float* R   = (const float*)d_in[16];
    const float* gamma1 = (const float*)d_in[17];
    const float* beta1  = (const float*)d_in[18];
    const float* gamma2 = (const float*)d_in[19];
    const float* beta2  = (const float*)d_in[20];

    const int nU = in_sizes[0] / 64;
    const int nV = in_sizes[1] / 64;
    const int n  = nU + nV;
    const int nE = in_sizes[2];

    float *pxvi, *py, *py2, *pst1, *pst2;
    unsigned *psuh;
    int *pcnt;
    cudaGetSymbolAddress((void**)&psuh, g_suh);
    cudaGetSymbolAddress((void**)&pxvi, g_xvi);
    cudaGetSymbolAddress((void**)&py,   g_y);
    cudaGetSymbolAddress((void**)&py2,  g_y2);
    cudaGetSymbolAddress((void**)&pst1, g_stats1);
    cudaGetSymbolAddress((void**)&pst2, g_stats2);
    cudaGetSymbolAddress((void**)&pcnt, g_cnt);

    cudaFuncSetAttribute(gemm4_kernel<false>, cudaFuncAttributeMaxDynamicSharedMemorySize, GEMM4_SMEM);
    cudaFuncSetAttribute(gemm4_kernel<true>,  cudaFuncAttributeMaxDynamicSharedMemorySize, GEMM4_SMEM);

    cudaMemsetAsync(pcnt, 0, (MAXN + 1) * sizeof(int));

    const int eb = (nE + 255) / 256;
    const int nb = (n + 255) / 256;
    const int nTiles = (n + 127) / 128;
    const int gemmBlocks  = nTiles < 296 ? nTiles : 296;
    const int finalBlocks = (n + 63) / 64;
    const int aggBlocks   = (n + 31) / 32;

    hist_kernel<<<eb, 256>>>(ee, nE);
    scan_block_kernel<<<nb, 256>>>(n);
    scan_add_kernel<<<nb, 256>>>(n);

    // ---- stage 1 GEMM (profiled slot #4) ----
    gemm4_kernel<false><<<gemmBlocks, 256, GEMM4_SMEM>>>(u, v, nU,
                                                         Ui1, Uj1, Vi1, Vj1, bu1, bv1,
                                                         nullptr, nullptr, nullptr,
                                                         psuh, py, pxvi, n);
    scatter_kernel<<<eb, 256>>>(es, ee, nE);
    agg_kernel<<<aggBlocks, 256>>>(pxvi, psuh, py, pst1, n);

    // ---- stage 2 (BN1+ReLU fused into X load) ----
    gemm4_kernel<true><<<gemmBlocks, 256, GEMM4_SMEM>>>(py, py, n,
                                                        Ui2, Uj2, Vi2, Vj2, bu2, bv2,
                                                        pst1, gamma1, beta1,
                                                        psuh, py2, pxvi, n);
    agg_kernel<<<aggBlocks, 256>>>(pxvi, psuh, py2, pst2, n);

    // ---- final: relu(BN2(y2) + x_in @ R) ----
    final_kernel<<<finalBlocks, 256>>>(u, v, nU, R, py2, pst2, gamma2, beta2, (float*)d_out, n);
}